// round 6
// baseline (speedup 1.0000x reference)
#include <cuda_runtime.h>
#include <cstdint>

#define BB 16
#define NN 4096
#define MM 1024
#define K0 32
#define K1 64
#define P0 (BB*MM*K0)     // 524288
#define P1 (BB*MM*K1)     // 1048576
#define OUT_OFS (BB*3*MM) // 49152
#define GCOUNT (BB*MM)    // 16384 pool groups per channel

#define FMA2(acc, x, w) asm("fma.rn.f32x2 %0, %1, %2, %0;" : "+l"(acc) : "l"(x), "l"(w))
#define PACK2(dst, f)   asm("mov.b64 %0, {%1, %1};" : "=l"(dst) : "r"(__float_as_uint(f)))

__device__ __forceinline__ float2 unpk(unsigned long long v) {
    return make_float2(__uint_as_float((unsigned)v), __uint_as_float((unsigned)(v >> 32)));
}

// ---------------- scratch (device globals; no allocation allowed) ----------------
__device__ int   g_samp[BB*MM];
__device__ int   g_idx0[P0];
__device__ int   g_idx1[P1];
__device__ float g_bufA[64*P1];    // 256 MB
__device__ float g_bufB[96*P1];    // 384 MB
__device__ float g_ft[BB*NN*64];   // transposed features (B,N,64)
__device__ float g_s[128];
__device__ float g_t[128];
__device__ float g_ps [128*4096];
__device__ float g_ps2[128*4096];
__device__ float g_pmax[128*GCOUNT];
__device__ float g_pmin[128*GCOUNT];
__device__ float g_wt [6*12288];

struct WPtrs { const float* w[6]; };

// ---------------- combined weight transpose + channel permute + out-pad ----------------
__global__ void wtr_kernel(WPtrs wp, float* __restrict__ wt)
{
    const int cins[6]   = {67, 64, 64, 67, 64, 96};
    const int cpads[6]  = {80, 64, 64, 80, 64, 96};
    const int couts[6]  = {64, 64, 128, 64, 96, 128};
    const int copads[6] = {64, 64, 128, 64, 128, 128};
    const int gat[6]    = {1, 0, 0, 1, 0, 0};
    int l = blockIdx.x;
    const float* W = wp.w[l];
    int cin = cins[l], cpad = cpads[l], cout = couts[l], copad = copads[l];
    float* dst = wt + l*12288;
    int total = cpad * copad;
    for (int e = threadIdx.x; e < total; e += 256) {
        int c = e / copad, o = e - c*copad;
        int src;
        if (gat[l]) src = (c < 64) ? c + 3 : (c < 67 ? c - 64 : -1);
        else        src = (c < cin) ? c : -1;
        dst[e] = (src >= 0 && o < cout) ? W[o*cin + src] : 0.0f;
    }
}

// ---------------- feature transpose: (B,64,N) -> (B,N,64) ----------------
__global__ __launch_bounds__(256) void ftr_kernel(const float* __restrict__ feat,
                                                  float* __restrict__ ft)
{
    __shared__ float tile[32][33];
    int b = blockIdx.z, c0 = blockIdx.y*32, n0 = blockIdx.x*32;
    int tx = threadIdx.x, ty = threadIdx.y;
#pragma unroll
    for (int k = 0; k < 4; k++) {
        int c = c0 + ty + k*8;
        tile[ty + k*8][tx] = feat[(size_t)(b*64 + c)*NN + n0 + tx];
    }
    __syncthreads();
#pragma unroll
    for (int k = 0; k < 4; k++) {
        int n = n0 + ty + k*8;
        ft[((size_t)b*NN + n)*64 + c0 + tx] = tile[tx][ty + k*8];
    }
}

// ---------------- FPS: one block per batch; REDUX-based argmax ----------------
__global__ __launch_bounds__(512) void fps_kernel(const float* __restrict__ pc,
                                                  int* __restrict__ samp,
                                                  float* __restrict__ dout)
{
    int b   = blockIdx.x;
    int tid = threadIdx.x;
    const float* px = pc + (size_t)b*3*NN;
    const float* py = px + NN;
    const float* pz = py + NN;

    float x[8], yv[8], z[8], dmin[8];
#pragma unroll
    for (int j = 0; j < 8; j++) {
        int i = tid + j*512;
        x[j] = px[i]; yv[j] = py[i]; z[j] = pz[i];
        dmin[j] = 1e10f;
    }

    __shared__ unsigned svu[16];
    __shared__ unsigned siu[16];
    __shared__ int sfar;

    int lane = tid & 31, w = tid >> 5;
    int far = 0;
    for (int it = 0; it < MM; it++) {
        if (tid == 0) {
            samp[b*MM + it] = far;
            dout[(b*3+0)*MM + it] = px[far];
            dout[(b*3+1)*MM + it] = py[far];
            dout[(b*3+2)*MM + it] = pz[far];
        }
        float cx = px[far], cy = py[far], cz = pz[far];

        float bv = -1.0f; int bi = 0;
#pragma unroll
        for (int j = 0; j < 8; j++) {
            float dx = x[j]  - cx;
            float dy = yv[j] - cy;
            float dz = z[j]  - cz;
            float d = __fadd_rn(__fadd_rn(__fmul_rn(dx,dx), __fmul_rn(dy,dy)), __fmul_rn(dz,dz));
            float nd = fminf(dmin[j], d);
            dmin[j] = nd;
            if (nd > bv) { bv = nd; bi = tid + j*512; }
        }
        unsigned fb = __float_as_uint(bv);
        unsigned mw = __reduce_max_sync(0xffffffffu, fb);
        unsigned ci = (fb == mw) ? (unsigned)bi : 0xffffffffu;
        unsigned mi = __reduce_min_sync(0xffffffffu, ci);
        if (lane == 0) { svu[w] = mw; siu[w] = mi; }
        __syncthreads();
        if (w == 0) {
            unsigned f2 = (tid < 16) ? svu[tid] : 0u;
            unsigned i2 = (tid < 16) ? siu[tid] : 0xffffffffu;
            unsigned m2 = __reduce_max_sync(0xffffffffu, f2);
            unsigned c2 = (f2 == m2) ? i2 : 0xffffffffu;
            unsigned r2 = __reduce_min_sync(0xffffffffu, c2);
            if (tid == 0) sfar = (int)r2;
        }
        __syncthreads();
        far = sfar;
    }
}

// ---------------- Fused dual-radius ball query: one scan, both K lists ----------------
__global__ __launch_bounds__(256) void ballquery2_kernel(const float* __restrict__ pc,
                                                         const int* __restrict__ samp,
                                                         int* __restrict__ gidx0,
                                                         int* __restrict__ gidx1,
                                                         float r2a, float r2b)
{
    extern __shared__ float sh[];
    float* sx = sh;
    float* sy = sh + NN;
    float* sz = sh + 2*NN;

    int b = blockIdx.x;
    const float* px = pc + (size_t)b*3*NN;
    for (int i = threadIdx.x; i < NN; i += blockDim.x) {
        sx[i] = px[i]; sy[i] = px[NN + i]; sz[i] = px[2*NN + i];
    }
    __syncthreads();

    int lane = threadIdx.x & 31;
    int wid  = threadIdx.x >> 5;
    int mstart = blockIdx.y * 32;
    unsigned lt = (1u << lane) - 1u;

    for (int m = mstart + wid; m < mstart + 32; m += 8) {
        int ci = samp[b*MM + m];
        float cx = sx[ci], cy = sy[ci], cz = sz[ci];
        int cnt0 = 0, cnt1 = 0, f0 = -1, f1 = -1;
        int* out0 = gidx0 + ((size_t)(b*MM + m))*K0;
        int* out1 = gidx1 + ((size_t)(b*MM + m))*K1;

        for (int base = 0; base < NN && (cnt0 < K0 || cnt1 < K1); base += 32) {
            int i = base + lane;
            float dx = sx[i] - cx;
            float dy = sy[i] - cy;
            float dz = sz[i] - cz;
            float d = __fadd_rn(__fadd_rn(__fmul_rn(dx,dx), __fmul_rn(dy,dy)), __fmul_rn(dz,dz));
            bool ok0 = d < r2a;
            bool ok1 = d < r2b;
            unsigned m0 = __ballot_sync(0xffffffffu, ok0);
            unsigned m1 = __ballot_sync(0xffffffffu, ok1);
            if (f0 < 0 && m0) f0 = base + __ffs(m0) - 1;
            if (f1 < 0 && m1) f1 = base + __ffs(m1) - 1;
            int p0 = cnt0 + __popc(m0 & lt);
            int p1 = cnt1 + __popc(m1 & lt);
            if (ok0 && p0 < K0) out0[p0] = i;
            if (ok1 && p1 < K1) out1[p1] = i;
            cnt0 = min(K0, cnt0 + __popc(m0));
            cnt1 = min(K1, cnt1 + __popc(m1));
        }
        for (int p = cnt0 + lane; p < K0; p += 32) out0[p] = f0;
        for (int p = cnt1 + lane; p < K1; p += 32) out1[p] = f1;
    }
}

// ---------------- Tiled GEMM: 64 out x 256 pos per block, FFMA2, 8x8 thread tile ----------------
template<bool GATHER, bool POOL>
__global__ __launch_bounds__(256, 2) void conv_kernel(
    const float* __restrict__ xin, const float* __restrict__ Wt,
    const float* __restrict__ bias,
    const float* __restrict__ bns, const float* __restrict__ bnt,
    float* __restrict__ y, float* __restrict__ ps, float* __restrict__ ps2,
    float* __restrict__ pmax, float* __restrict__ pmin,
    int cin, int nk, int cout, int copad, int P, int K,
    const float* __restrict__ pc, const float* __restrict__ ft,
    const float* __restrict__ newpc, const int* __restrict__ gidx,
    int mkshift, int kshift)
{
    __shared__ __align__(16) float xs[2][16][256];
    __shared__ __align__(16) float ws[2][16][64];
    __shared__ float ssA[96], stA[96];
    __shared__ int sidx[256];

    const int tx = threadIdx.x, ty = threadIdx.y;
    const int t  = ty*32 + tx;
    const int pblock = blockIdx.x * 256;
    const int oblock = blockIdx.y * 64;
    const int nblk = gridDim.x;

    if (GATHER) {
        sidx[t] = gidx[pblock + t];
    } else {
        if (t < cin) { ssA[t] = bns[t]; stA[t] = bnt[t]; }
    }
    __syncthreads();

    int g_bb = 0, g_mm = 0, g_ix = 0;
    size_t g_fb = 0;
    if (GATHER) {
        int p = pblock + t;
        g_bb = p >> mkshift;
        g_mm = (p >> kshift) & (MM - 1);
        g_ix = sidx[t];
        g_fb = ((size_t)g_bb*NN + g_ix)*64;
    }

    float4 xr[4];
    float  gxr[16];
    float4 wr = make_float4(0,0,0,0);
    const int wcc = t >> 4, wo4 = t & 15;

    auto load_x = [&](int kc) {
        if (GATHER) {
            if (kc < 4) {
#pragma unroll
                for (int j = 0; j < 4; j++) {
                    float4 v = *(const float4*)&ft[g_fb + kc*16 + j*4];
                    gxr[j*4+0] = v.x; gxr[j*4+1] = v.y; gxr[j*4+2] = v.z; gxr[j*4+3] = v.w;
                }
            } else {
#pragma unroll
                for (int i = 0; i < 16; i++) gxr[i] = 0.0f;
#pragma unroll
                for (int d = 0; d < 3; d++)
                    gxr[d] = pc[(size_t)(g_bb*3 + d)*NN + g_ix] - newpc[(size_t)(g_bb*3 + d)*MM + g_mm];
            }
        } else {
            int c0 = kc * 16;
#pragma unroll
            for (int i = 0; i < 4; i++) {
                int f  = t + i*256;
                int cc = f >> 6, q = f & 63;
                int c  = c0 + cc;
                float4 v = *(const float4*)&xin[(size_t)c*P + pblock + q*4];
                float sc = ssA[c], tc = stA[c];
                v.x = fmaxf(v.x*sc + tc, 0.0f);
                v.y = fmaxf(v.y*sc + tc, 0.0f);
                v.z = fmaxf(v.z*sc + tc, 0.0f);
                v.w = fmaxf(v.w*sc + tc, 0.0f);
                xr[i] = v;
            }
        }
    };
    auto load_w = [&](int kc) {
        wr = *(const float4*)&Wt[(size_t)(kc*16 + wcc)*copad + oblock + wo4*4];
    };
    auto store_stage = [&](int buf) {
        if (GATHER) {
#pragma unroll
            for (int i = 0; i < 16; i++) xs[buf][i][t] = gxr[i];
        } else {
#pragma unroll
            for (int i = 0; i < 4; i++) {
                int f  = t + i*256;
                int cc = f >> 6, q = f & 63;
                *(float4*)&xs[buf][cc][q*4] = xr[i];
            }
        }
        *(float4*)&ws[buf][wcc][wo4*4] = wr;
    };

    unsigned long long acc[8][4];
#pragma unroll
    for (int o = 0; o < 8; o++)
#pragma unroll
        for (int p = 0; p < 4; p++) acc[o][p] = 0ULL;

    load_x(0); load_w(0); store_stage(0);
    __syncthreads();

    for (int kc = 0; kc < nk; kc++) {
        int buf = kc & 1;
        if (kc + 1 < nk) { load_x(kc + 1); load_w(kc + 1); }
#pragma unroll
        for (int cc = 0; cc < 16; cc++) {
            float4 w0 = *(const float4*)&ws[buf][cc][ty*8];
            float4 w1 = *(const float4*)&ws[buf][cc][ty*8 + 4];
            ulonglong2 a01 = *(const ulonglong2*)&xs[buf][cc][tx*4];
            ulonglong2 b01 = *(const ulonglong2*)&xs[buf][cc][128 + tx*4];
            unsigned long long wp0, wp1, wp2, wp3, wp4, wp5, wp6, wp7;
            PACK2(wp0, w0.x); PACK2(wp1, w0.y); PACK2(wp2, w0.z); PACK2(wp3, w0.w);
            PACK2(wp4, w1.x); PACK2(wp5, w1.y); PACK2(wp6, w1.z); PACK2(wp7, w1.w);
            FMA2(acc[0][0], a01.x, wp0); FMA2(acc[0][1], a01.y, wp0);
            FMA2(acc[0][2], b01.x, wp0); FMA2(acc[0][3], b01.y, wp0);
            FMA2(acc[1][0], a01.x, wp1); FMA2(acc[1][1], a01.y, wp1);
            FMA2(acc[1][2], b01.x, wp1); FMA2(acc[1][3], b01.y, wp1);
            FMA2(acc[2][0], a01.x, wp2); FMA2(acc[2][1], a01.y, wp2);
            FMA2(acc[2][2], b01.x, wp2); FMA2(acc[2][3], b01.y, wp2);
            FMA2(acc[3][0], a01.x, wp3); FMA2(acc[3][1], a01.y, wp3);
            FMA2(acc[3][2], b01.x, wp3); FMA2(acc[3][3], b01.y, wp3);
            FMA2(acc[4][0], a01.x, wp4); FMA2(acc[4][1], a01.y, wp4);
            FMA2(acc[4][2], b01.x, wp4); FMA2(acc[4][3], b01.y, wp4);
            FMA2(acc[5][0], a01.x, wp5); FMA2(acc[5][1], a01.y, wp5);
            FMA2(acc[5][2], b01.x, wp5); FMA2(acc[5][3], b01.y, wp5);
            FMA2(acc[6][0], a01.x, wp6); FMA2(acc[6][1], a01.y, wp6);
            FMA2(acc[6][2], b01.x, wp6); FMA2(acc[6][3], b01.y, wp6);
            FMA2(acc[7][0], a01.x, wp7); FMA2(acc[7][1], a01.y, wp7);
            FMA2(acc[7][2], b01.x, wp7); FMA2(acc[7][3], b01.y, wp7);
        }
        if (kc + 1 < nk) store_stage(buf ^ 1);
        __syncthreads();
    }

    int pbase0 = pblock + tx*4;
#pragma unroll
    for (int o = 0; o < 8; o++) {
        int oc = oblock + ty*8 + o;
        bool valid = (oc < cout);
        float bv = valid ? bias[oc] : 0.0f;
        float2 u0 = unpk(acc[o][0]);
        float2 u1 = unpk(acc[o][1]);
        float2 u2 = unpk(acc[o][2]);
        float2 u3 = unpk(acc[o][3]);
        float4 r0 = make_float4(u0.x+bv, u0.y+bv, u1.x+bv, u1.y+bv);
        float4 r1 = make_float4(u2.x+bv, u2.y+bv, u3.x+bv, u3.y+bv);
        if (!POOL && valid) {
            *(float4*)&y[(size_t)oc*P + pbase0]       = r0;
            *(float4*)&y[(size_t)oc*P + pbase0 + 128] = r1;
        }
        float s1 = ((r0.x+r0.y)+(r0.z+r0.w)) + ((r1.x+r1.y)+(r1.z+r1.w));
        float s2 = (r0.x*r0.x + r0.y*r0.y + r0.z*r0.z + r0.w*r0.w)
                 + (r1.x*r1.x + r1.y*r1.y + r1.z*r1.z + r1.w*r1.w);
#pragma unroll
        for (int off = 16; off > 0; off >>= 1) {
            s1 += __shfl_down_sync(0xffffffffu, s1, off);
            s2 += __shfl_down_sync(0xffffffffu, s2, off);
        }
        if (tx == 0 && valid) {
            ps [(size_t)oc*nblk + blockIdx.x] = s1;
            ps2[(size_t)oc*nblk + blockIdx.x] = s2;
        }
        if (POOL) {
            float mxA = fmaxf(fmaxf(r0.x, r0.y), fmaxf(r0.z, r0.w));
            float mnA = fminf(fminf(r0.x, r0.y), fminf(r0.z, r0.w));
            float mxB = fmaxf(fmaxf(r1.x, r1.y), fmaxf(r1.z, r1.w));
            float mnB = fminf(fminf(r1.x, r1.y), fminf(r1.z, r1.w));
            if (K == 32) {
#pragma unroll
                for (int off = 4; off > 0; off >>= 1) {
                    mxA = fmaxf(mxA, __shfl_xor_sync(0xffffffffu, mxA, off));
                    mnA = fminf(mnA, __shfl_xor_sync(0xffffffffu, mnA, off));
                    mxB = fmaxf(mxB, __shfl_xor_sync(0xffffffffu, mxB, off));
                    mnB = fminf(mnB, __shfl_xor_sync(0xffffffffu, mnB, off));
                }
                if ((tx & 7) == 0 && valid) {
                    int gA = (pblock >> 5) + (tx >> 3);
                    int gB = gA + 4;
                    pmax[(size_t)oc*GCOUNT + gA] = mxA;
                    pmin[(size_t)oc*GCOUNT + gA] = mnA;
                    pmax[(size_t)oc*GCOUNT + gB] = mxB;
                    pmin[(size_t)oc*GCOUNT + gB] = mnB;
                }
            } else { // K == 64
#pragma unroll
                for (int off = 8; off > 0; off >>= 1) {
                    mxA = fmaxf(mxA, __shfl_xor_sync(0xffffffffu, mxA, off));
                    mnA = fminf(mnA, __shfl_xor_sync(0xffffffffu, mnA, off));
                    mxB = fmaxf(mxB, __shfl_xor_sync(0xffffffffu, mxB, off));
                    mnB = fminf(mnB, __shfl_xor_sync(0xffffffffu, mnB, off));
                }
                if ((tx & 15) == 0 && valid) {
                    int gA = (pblock >> 6) + (tx >> 4);
                    int gB = gA + 2;
                    pmax[(size_t)oc*GCOUNT + gA] = mxA;
                    pmin[(size_t)oc*GCOUNT + gA] = mnA;
                    pmax[(size_t)oc*GCOUNT + gB] = mxB;
                    pmin[(size_t)oc*GCOUNT + gB] = mnB;
                }
            }
        }
    }
}

// ---------------- finalize BN: reduce partials -> (scale, shift) ----------------
__global__ __launch_bounds__(256) void finalize_kernel(const float* __restrict__ ps,
                                                       const float* __restrict__ ps2,
                                                       int nblk, float invP,
                                                       const float* __restrict__ gamma,
                                                       const float* __restrict__ beta,
                                                       float* __restrict__ s,
                                                       float* __restrict__ t)
{
    int c = blockIdx.x;
    float a = 0.0f, b = 0.0f;
    for (int i = threadIdx.x; i < nblk; i += 256) {
        a += ps [(size_t)c*nblk + i];
        b += ps2[(size_t)c*nblk + i];
    }
#pragma unroll
    for (int off = 16; off > 0; off >>= 1) {
        a += __shfl_down_sync(0xffffffffu, a, off);
        b += __shfl_down_sync(0xffffffffu, b, off);
    }
    __shared__ float sa[8], sb[8];
    int lane = threadIdx.x & 31, w = threadIdx.x >> 5;
    if (lane == 0) { sa[w] = a; sb[w] = b; }
    __syncthreads();
    if (threadIdx.x < 8) {
        a = sa[threadIdx.x]; b = sb[threadIdx.x];
#pragma unroll
        for (int off = 4; off > 0; off >>= 1) {
            a += __shfl_down_sync(0xffu, a, off);
            b += __shfl_down_sync(0xffu, b, off);
        }
        if (threadIdx.x == 0) {
            float mu  = a * invP;
            float var = b * invP - mu*mu;
            float rs  = 1.0f / sqrtf(var + 1e-5f);
            float sc  = gamma[c] * rs;
            s[c] = sc;
            t[c] = beta[c] - mu * sc;
        }
    }
}

// ---------------- apply BN to pooled max/min, write output ----------------
__global__ __launch_bounds__(256) void pool_apply_kernel(const float* __restrict__ pmax,
                                                         const float* __restrict__ pmin,
                                                         const float* __restrict__ s,
                                                         const float* __restrict__ t,
                                                         float* __restrict__ out,
                                                         int chbase)
{
    int gid = blockIdx.x*256 + threadIdx.x;
    int oc = gid >> 14;
    int g  = gid & 16383;
    float sc = s[oc], tc = t[oc];
    float v  = (sc > 0.0f) ? pmax[gid] : pmin[gid];
    float r  = fmaxf(v*sc + tc, 0.0f);
    int b = g >> 10, m = g & 1023;
    out[OUT_OFS + ((size_t)(b*256 + chbase + oc))*MM + m] = r;
}

// ---------------- host launch sequence ----------------
extern "C" void kernel_launch(void* const* d_in, const int* in_sizes, int n_in,
                              void* d_out, int out_size)
{
    const float* pc   = (const float*)d_in[0];
    const float* feat = (const float*)d_in[1];
    const float *Wp[6], *bp[6], *gp[6], *bep[6];
    for (int i = 0; i < 6; i++) {
        Wp[i]  = (const float*)d_in[2 + 4*i];
        bp[i]  = (const float*)d_in[3 + 4*i];
        gp[i]  = (const float*)d_in[4 + 4*i];
        bep[i] = (const float*)d_in[5 + 4*i];
    }
    float* out = (float*)d_out;

    int *samp, *idx0, *idx1;
    float *bufA, *bufB, *ft, *sv, *tv, *ps, *ps2, *pmax, *pmin, *wt;
    cudaGetSymbolAddress((void**)&samp, g_samp);
    cudaGetSymbolAddress((void**)&idx0, g_idx0);
    cudaGetSymbolAddress((void**)&idx1, g_idx1);
    cudaGetSymbolAddress((void**)&bufA, g_bufA);
    cudaGetSymbolAddress((void**)&bufB, g_bufB);
    cudaGetSymbolAddress((void**)&ft,   g_ft);
    cudaGetSymbolAddress((void**)&sv,   g_s);
    cudaGetSymbolAddress((void**)&tv,   g_t);
    cudaGetSymbolAddress((void**)&ps,   g_ps);
    cudaGetSymbolAddress((void**)&ps2,  g_ps2);
    cudaGetSymbolAddress((void**)&pmax, g_pmax);
    cudaGetSymbolAddress((void**)&pmin, g_pmin);
    cudaGetSymbolAddress((void**)&wt,   g_wt);

    const float r2_0 = (float)(0.1*0.1);
    const float r2_1 = (float)(0.2*0.2);

    WPtrs wargs;
    for (int l = 0; l < 6; l++) wargs.w[l] = Wp[l];
    wtr_kernel<<<6, 256>>>(wargs, wt);
    ftr_kernel<<<dim3(128, 2, BB), dim3(32, 8)>>>(feat, ft);
    fps_kernel<<<BB, 512>>>(pc, samp, out);
    ballquery2_kernel<<<dim3(BB,32), 256, 3*NN*sizeof(float)>>>(pc, samp, idx0, idx1, r2_0, r2_1);

    dim3 tb(32, 8);
    const int nbx0 = P0/256, nbx1 = P1/256;

    // -------- branch 0 (K=32): 67 -> 64 -> 64 -> 128 --------
    conv_kernel<true,false><<<dim3(nbx0, 1), tb>>>(nullptr, wt + 0*12288, bp[0], nullptr, nullptr,
        bufA, ps, ps2, nullptr, nullptr, 67, 5, 64, 64, P0, K0, pc, ft, out, idx0, 15, 5);
    finalize_kernel<<<64, 256>>>(ps, ps2, nbx0, 1.0f/(float)P0, gp[0], bep[0], sv, tv);
    conv_kernel<false,false><<<dim3(nbx0, 1), tb>>>(bufA, wt + 1*12288, bp[1], sv, tv,
        bufB, ps, ps2, nullptr, nullptr, 64, 4, 64, 64, P0, K0, nullptr, nullptr, nullptr, nullptr, 0, 0);
    finalize_kernel<<<64, 256>>>(ps, ps2, nbx0, 1.0f/(float)P0, gp[1], bep[1], sv, tv);
    conv_kernel<false,true><<<dim3(nbx0, 2), tb>>>(bufB, wt + 2*12288, bp[2], sv, tv,
        nullptr, ps, ps2, pmax, pmin, 64, 4, 128, 128, P0, K0, nullptr, nullptr, nullptr, nullptr, 0, 0);
    finalize_kernel<<<128, 256>>>(ps, ps2, nbx0, 1.0f/(float)P0, gp[2], bep[2], sv, tv);
    pool_apply_kernel<<<(128*GCOUNT)/256, 256>>>(pmax, pmin, sv, tv, out, 0);

    // -------- branch 1 (K=64): 67 -> 64 -> 96 -> 128 --------
    conv_kernel<true,false><<<dim3(nbx1, 1), tb>>>(nullptr, wt + 3*12288, bp[3], nullptr, nullptr,
        bufA, ps, ps2, nullptr, nullptr, 67, 5, 64, 64, P1, K1, pc, ft, out, idx1, 16, 6);
    finalize_kernel<<<64, 256>>>(ps, ps2, nbx1, 1.0f/(float)P1, gp[3], bep[3], sv, tv);
    conv_kernel<false,false><<<dim3(nbx1, 2), tb>>>(bufA, wt + 4*12288, bp[4], sv, tv,
        bufB, ps, ps2, nullptr, nullptr, 64, 4, 96, 128, P1, K1, nullptr, nullptr, nullptr, nullptr, 0, 0);
    finalize_kernel<<<96, 256>>>(ps, ps2, nbx1, 1.0f/(float)P1, gp[4], bep[4], sv, tv);
    conv_kernel<false,true><<<dim3(nbx1, 2), tb>>>(bufB, wt + 5*12288, bp[5], sv, tv,
        nullptr, ps, ps2, pmax, pmin, 96, 6, 128, 128, P1, K1, nullptr, nullptr, nullptr, nullptr, 0, 0);
    finalize_kernel<<<128, 256>>>(ps, ps2, nbx1, 1.0f/(float)P1, gp[5], bep[5], sv, tv);
    pool_apply_kernel<<<(128*GCOUNT)/256, 256>>>(pmax, pmin, sv, tv, out, 128);
}

// round 8
// speedup vs baseline: 1.0711x; 1.0711x over previous
#include <cuda_runtime.h>
#include <cstdint>

#define BB 16
#define NN 4096
#define MM 1024
#define P0 (BB*MM*32)
#define P1 (BB*MM*64)
#define OUT_OFS (BB*3*MM)
#define GCOUNT (BB*MM)

__device__ int      g_samp[BB*MM];
__device__ int      g_idx0[P0];
__device__ int      g_idx1[P1];
__device__ float    g_bufA[64*P1];
__device__ float    g_bufB[96*P1];
__device__ float    g_ft[BB*NN*64];
__device__ float    g_s[128];
__device__ float    g_t[128];
__device__ float    g_ps [128*8192];
__device__ float    g_ps2[128*8192];
__device__ float    g_pmax[128*GCOUNT];
__device__ float    g_pmin[128*GCOUNT];
__device__ uint16_t g_wth[6*12288];
__device__ uint16_t g_wtl[6*12288];

struct WPtrs { const float* w[6]; };

__device__ __forceinline__ uint32_t smem_u32(const void* p) {
    uint32_t a;
    asm("{ .reg .u64 t; cvta.to.shared.u64 t, %1; cvt.u32.u64 %0, t; }" : "=r"(a) : "l"(p));
    return a;
}
__device__ __forceinline__ uint32_t packbf(float hi, float lo) {
    uint32_t d;
    asm("cvt.rn.bf16x2.f32 %0, %1, %2;" : "=r"(d) : "f"(hi), "f"(lo));
    return d;
}
#define LDSMX4(r, addr) \
    asm volatile("ldmatrix.sync.aligned.m8n8.x4.shared.b16 {%0,%1,%2,%3}, [%4];" \
        : "=r"((r)[0]), "=r"((r)[1]), "=r"((r)[2]), "=r"((r)[3]) : "r"(addr))
#define MMABF(c, a, b0v, b1v) \
    asm volatile("mma.sync.aligned.m16n8k16.row.col.f32.bf16.bf16.f32 " \
        "{%0,%1,%2,%3}, {%4,%5,%6,%7}, {%8,%9}, {%0,%1,%2,%3};" \
        : "+f"((c)[0]), "+f"((c)[1]), "+f"((c)[2]), "+f"((c)[3]) \
        : "r"((a)[0]), "r"((a)[1]), "r"((a)[2]), "r"((a)[3]), "r"(b0v), "r"(b1v))

// ---------------- weights: permute + bf16 hi/lo split, [l][out][cpad] ----------------
__global__ void wtr_kernel(WPtrs wp, uint16_t* __restrict__ wth, uint16_t* __restrict__ wtl)
{
    const int cins[6]  = {67, 64, 64, 67, 64, 96};
    const int cpads[6] = {80, 64, 64, 80, 64, 96};
    const int couts[6] = {64, 64, 128, 64, 96, 128};
    const int gat[6]   = {1, 0, 0, 1, 0, 0};
    int l = blockIdx.x;
    const float* W = wp.w[l];
    int cin = cins[l], cpad = cpads[l], cout = couts[l];
    for (int e = threadIdx.x; e < cout*cpad; e += 256) {
        int o = e / cpad, c = e - o*cpad;
        int src;
        if (gat[l]) src = (c < 64) ? c + 3 : (c < 67 ? c - 64 : -1);
        else        src = (c < cin) ? c : -1;
        float wf = (src >= 0) ? W[o*cin + src] : 0.0f;
        uint16_t h = (uint16_t)(packbf(wf, 0.0f) >> 16);
        float hf = __uint_as_float((uint32_t)h << 16);
        wth[l*12288 + e] = h;
        wtl[l*12288 + e] = (uint16_t)(packbf(wf - hf, 0.0f) >> 16);
    }
}

// ---------------- feature transpose ----------------
__global__ __launch_bounds__(256) void ftr_kernel(const float* __restrict__ feat,
                                                  float* __restrict__ ft)
{
    __shared__ float tile[32][33];
    int b = blockIdx.z, c0 = blockIdx.y*32, n0 = blockIdx.x*32;
    int tx = threadIdx.x, ty = threadIdx.y;
#pragma unroll
    for (int k = 0; k < 4; k++)
        tile[ty + k*8][tx] = feat[(size_t)(b*64 + c0 + ty + k*8)*NN + n0 + tx];
    __syncthreads();
#pragma unroll
    for (int k = 0; k < 4; k++)
        ft[((size_t)b*NN + n0 + ty + k*8)*64 + c0 + tx] = tile[tx][ty + k*8];
}

// ---------------- FPS ----------------
__global__ __launch_bounds__(512) void fps_kernel(const float* __restrict__ pc,
                                                  int* __restrict__ samp,
                                                  float* __restrict__ dout)
{
    int b = blockIdx.x, tid = threadIdx.x;
    const float* px = pc + (size_t)b*3*NN;
    const float* py = px + NN;
    const float* pz = py + NN;
    float x[8], yv[8], z[8], dmin[8];
#pragma unroll
    for (int j = 0; j < 8; j++) {
        int i = tid + j*512;
        x[j] = px[i]; yv[j] = py[i]; z[j] = pz[i]; dmin[j] = 1e10f;
    }
    __shared__ unsigned svu[16], siu[16];
    __shared__ int sfar;
    int lane = tid & 31, w = tid >> 5, far = 0;
    for (int it = 0; it < MM; it++) {
        if (tid == 0) {
            samp[b*MM + it] = far;
            dout[(b*3+0)*MM + it] = px[far];
            dout[(b*3+1)*MM + it] = py[far];
            dout[(b*3+2)*MM + it] = pz[far];
        }
        float cx = px[far], cy = py[far], cz = pz[far];
        float bv = -1.0f; int bi = 0;
#pragma unroll
        for (int j = 0; j < 8; j++) {
            float dx = x[j]-cx, dy = yv[j]-cy, dz = z[j]-cz;
            float d = __fadd_rn(__fadd_rn(__fmul_rn(dx,dx), __fmul_rn(dy,dy)), __fmul_rn(dz,dz));
            float nd = fminf(dmin[j], d);
            dmin[j] = nd;
            if (nd > bv) { bv = nd; bi = tid + j*512; }
        }
        unsigned fb = __float_as_uint(bv);
        unsigned mw = __reduce_max_sync(0xffffffffu, fb);
        unsigned mi = __reduce_min_sync(0xffffffffu, (fb == mw) ? (unsigned)bi : 0xffffffffu);
        if (lane == 0) { svu[w] = mw; siu[w] = mi; }
        __syncthreads();
        if (w == 0) {
            unsigned f2 = (tid < 16) ? svu[tid] : 0u;
            unsigned i2 = (tid < 16) ? siu[tid] : 0xffffffffu;
            unsigned m2 = __reduce_max_sync(0xffffffffu, f2);
            unsigned r2 = __reduce_min_sync(0xffffffffu, (f2 == m2) ? i2 : 0xffffffffu);
            if (tid == 0) sfar = (int)r2;
        }
        __syncthreads();
        far = sfar;
    }
}

// ---------------- dual-radius ball query ----------------
__global__ __launch_bounds__(256) void ballquery2_kernel(const float* __restrict__ pc,
    const int* __restrict__ samp, int* __restrict__ gidx0, int* __restrict__ gidx1,
    float r2a, float r2b)
{
    extern __shared__ float sh[];
    float* sx = sh; float* sy = sh + NN; float* sz = sh + 2*NN;
    int b = blockIdx.x;
    const float* px = pc + (size_t)b*3*NN;
    for (int i = threadIdx.x; i < NN; i += blockDim.x) {
        sx[i] = px[i]; sy[i] = px[NN+i]; sz[i] = px[2*NN+i];
    }
    __syncthreads();
    int lane = threadIdx.x & 31, wid = threadIdx.x >> 5;
    int mstart = blockIdx.y * 32;
    unsigned lt = (1u << lane) - 1u;
    for (int m = mstart + wid; m < mstart + 32; m += 8) {
        int ci = samp[b*MM + m];
        float cx = sx[ci], cy = sy[ci], cz = sz[ci];
        int cnt0 = 0, cnt1 = 0, f0 = -1, f1 = -1;
        int* out0 = gidx0 + ((size_t)(b*MM + m))*32;
        int* out1 = gidx1 + ((size_t)(b*MM + m))*64;
        for (int base = 0; base < NN && (cnt0 < 32 || cnt1 < 64); base += 32) {
            int i = base + lane;
            float dx = sx[i]-cx, dy = sy[i]-cy, dz = sz[i]-cz;
            float d = __fadd_rn(__fadd_rn(__fmul_rn(dx,dx), __fmul_rn(dy,dy)), __fmul_rn(dz,dz));
            bool ok0 = d < r2a, ok1 = d < r2b;
            unsigned m0 = __ballot_sync(0xffffffffu, ok0);
            unsigned m1 = __ballot_sync(0xffffffffu, ok1);
            if (f0 < 0 && m0) f0 = base + __ffs(m0) - 1;
            if (f1 < 0 && m1) f1 = base + __ffs(m1) - 1;
            int p0 = cnt0 + __popc(m0 & lt);
            int p1 = cnt1 + __popc(m1 & lt);
            if (ok0 && p0 < 32) out0[p0] = i;
            if (ok1 && p1 < 64) out1[p1] = i;
            cnt0 = min(32, cnt0 + __popc(m0));
            cnt1 = min(64, cnt1 + __popc(m1));
        }
        for (int p = cnt0 + lane; p < 32; p += 32) out0[p] = f0;
        for (int p = cnt1 + lane; p < 64; p += 32) out1[p] = f1;
    }
}

// ---------------- tensor-core conv: 128 pos x COUT per block, bf16 3-term ----------------
template<bool GATHER, bool POOL, int COUT, int CPAD, int KP>
__global__ __launch_bounds__(256) void conv_mma(
    const float* __restrict__ xin,
    const uint16_t* __restrict__ Whi, const uint16_t* __restrict__ Wlo,
    const float* __restrict__ bias,
    const float* __restrict__ bns, const float* __restrict__ bnt,
    float* __restrict__ y, float* __restrict__ ps, float* __restrict__ ps2,
    float* __restrict__ pmax, float* __restrict__ pmin,
    const float* __restrict__ pc, const float* __restrict__ ft,
    const float* __restrict__ newpc, const int* __restrict__ gidx,
    int mkshift, int kshift)
{
    constexpr int NK = CPAD/16;
    constexpr int WSTR = CPAD*2 + 16;
    constexpr int XROW = 48, XPLANE = 128*XROW;
    constexpr int WOFF = 4*XPLANE;
    constexpr int MOFF = WOFF + 2*COUT*WSTR;

    extern __shared__ __align__(16) unsigned char smem[];
    float* ssA = (float*)(smem + MOFF);
    float* stA = (float*)(smem + MOFF + 512);
    unsigned* sfb = (unsigned*)(smem + MOFF + 1024);
    float* sdx = (float*)(smem + MOFF + 1536);
    float* sdy = (float*)(smem + MOFF + 2048);
    float* sdz = (float*)(smem + MOFF + 2560);
    float* sm1 = (float*)(smem + MOFF + 3072);
    float* sm2 = sm1 + 8*COUT;
    float* pmx = sm2 + 8*COUT;
    float* pmn = pmx + 8*COUT;

    const int tid = threadIdx.x, lane = tid & 31, w = tid >> 5;
    const int pblock = blockIdx.x * 128;
    const int nblk = gridDim.x;

    if (GATHER) {
        if (tid < 128) {
            int p = pblock + tid;
            int bbv = p >> mkshift, mmv = (p >> kshift) & (MM-1);
            int ix = gidx[p];
            sfb[tid] = (unsigned)((bbv*NN + ix) * 64);
            sdx[tid] = pc[(size_t)(bbv*3+0)*NN+ix] - newpc[(size_t)(bbv*3+0)*MM+mmv];
            sdy[tid] = pc[(size_t)(bbv*3+1)*NN+ix] - newpc[(size_t)(bbv*3+1)*MM+mmv];
            sdz[tid] = pc[(size_t)(bbv*3+2)*NN+ix] - newpc[(size_t)(bbv*3+2)*MM+mmv];
        }
    } else {
        if (tid < CPAD) { ssA[tid] = bns[tid]; stA[tid] = bnt[tid]; }
    }
    for (int e = tid; e < COUT*CPAD/2; e += 256) {
        int o = e / (CPAD/2), cp = e - o*(CPAD/2);
        *(uint32_t*)(smem + WOFF + o*WSTR + cp*4) = ((const uint32_t*)Whi)[e];
        *(uint32_t*)(smem + WOFF + COUT*WSTR + o*WSTR + cp*4) = ((const uint32_t*)Wlo)[e];
    }
    __syncthreads();   // init + W staging visible before stage() reads sfb/ssA

    auto stage = [&](int kc, int buf) {
        unsigned char* xh = smem + (buf*2+0)*XPLANE;
        unsigned char* xl = smem + (buf*2+1)*XPLANE;
        for (int e = tid; e < 512; e += 256) {
            int pos = e >> 2, c4 = e & 3;
            float4 v;
            if (GATHER) {
                if (kc < 4) v = *(const float4*)&ft[sfb[pos] + kc*16 + c4*4];
                else v = (c4 == 0) ? make_float4(sdx[pos], sdy[pos], sdz[pos], 0.f)
                                   : make_float4(0.f, 0.f, 0.f, 0.f);
            } else {
                int c0 = kc*16 + c4*4;
                v = *(const float4*)&xin[(size_t)(pblock+pos)*CPAD + c0];
                float4 sc = *(float4*)&ssA[c0];
                float4 tc = *(float4*)&stA[c0];
                v.x = fmaxf(v.x*sc.x+tc.x, 0.f); v.y = fmaxf(v.y*sc.y+tc.y, 0.f);
                v.z = fmaxf(v.z*sc.z+tc.z, 0.f); v.w = fmaxf(v.w*sc.w+tc.w, 0.f);
            }
            uint32_t h0 = packbf(v.y, v.x), h1 = packbf(v.w, v.z);
            float rx = __uint_as_float(h0 << 16), ry = __uint_as_float(h0 & 0xffff0000u);
            float rz = __uint_as_float(h1 << 16), rw = __uint_as_float(h1 & 0xffff0000u);
            uint32_t off = pos*XROW + c4*8;
            *(uint2*)(xh + off) = make_uint2(h0, h1);
            *(uint2*)(xl + off) = make_uint2(packbf(v.y-ry, v.x-rx), packbf(v.w-rw, v.z-rz));
        }
    };

    const uint32_t base = smem_u32(smem);
    const uint32_t aoff = base + (uint32_t)((w*16 + (lane & 15))*XROW + (lane >> 4)*16);
    const uint32_t boff = base + WOFF +
        (uint32_t)((((lane >> 4) & 1)*8 + (lane & 7))*WSTR + ((lane >> 3) & 1)*16);

    float acc[COUT/8][4];
#pragma unroll
    for (int n = 0; n < COUT/8; n++)
#pragma unroll
        for (int c = 0; c < 4; c++) acc[n][c] = 0.f;

    stage(0, 0);
    __syncthreads();

    for (int kc = 0; kc < NK; kc++) {
        int buf = kc & 1;
        uint32_t ah[4], al[4];
        LDSMX4(ah, aoff + (buf*2+0)*XPLANE);
        LDSMX4(al, aoff + (buf*2+1)*XPLANE);
#pragma unroll
        for (int j = 0; j < COUT/16; j++) {
            uint32_t bh[4], bl[4];
            LDSMX4(bh, boff + j*16*WSTR + kc*32);
            LDSMX4(bl, boff + COUT*WSTR + j*16*WSTR + kc*32);
            MMABF(acc[2*j],   ah, bh[0], bh[1]);
            MMABF(acc[2*j+1], ah, bh[2], bh[3]);
            MMABF(acc[2*j],   ah, bl[0], bl[1]);
            MMABF(acc[2*j+1], ah, bl[2], bl[3]);
            MMABF(acc[2*j],   al, bh[0], bh[1]);
            MMABF(acc[2*j+1], al, bh[2], bh[3]);
        }
        if (kc + 1 < NK) stage(kc + 1, buf ^ 1);
        __syncthreads();
    }

    const int q = lane >> 2;
    const int r2i = (lane & 3) * 2;
#pragma unroll
    for (int nt = 0; nt < COUT/8; nt++) {
        int oc = nt*8 + r2i;
        float2 bv = *(const float2*)&bias[oc];
        float2 c01 = make_float2(acc[nt][0]+bv.x, acc[nt][1]+bv.y);
        float2 c23 = make_float2(acc[nt][2]+bv.x, acc[nt][3]+bv.y);
        if (!POOL) {
            *(float2*)&y[(size_t)(pblock + w*16 + q)*COUT + oc]     = c01;
            *(float2*)&y[(size_t)(pblock + w*16 + q + 8)*COUT + oc] = c23;
        }
        float s1x = c01.x + c23.x, s1y = c01.y + c23.y;
        float s2x = c01.x*c01.x + c23.x*c23.x, s2y = c01.y*c01.y + c23.y*c23.y;
        float mxx = fmaxf(c01.x, c23.x), mxy = fmaxf(c01.y, c23.y);
        float mnx = fminf(c01.x, c23.x), mny = fminf(c01.y, c23.y);
#pragma unroll
        for (int o2 = 4; o2 <= 16; o2 <<= 1) {
            s1x += __shfl_xor_sync(0xffffffffu, s1x, o2);
            s1y += __shfl_xor_sync(0xffffffffu, s1y, o2);
            s2x += __shfl_xor_sync(0xffffffffu, s2x, o2);
            s2y += __shfl_xor_sync(0xffffffffu, s2y, o2);
            if (POOL) {
                mxx = fmaxf(mxx, __shfl_xor_sync(0xffffffffu, mxx, o2));
                mxy = fmaxf(mxy, __shfl_xor_sync(0xffffffffu, mxy, o2));
                mnx = fminf(mnx, __shfl_xor_sync(0xffffffffu, mnx, o2));
                mny = fminf(mny, __shfl_xor_sync(0xffffffffu, mny, o2));
            }
        }
        if (q == 0) {
            sm1[w*COUT + oc] = s1x; sm1[w*COUT + oc + 1] = s1y;
            sm2[w*COUT + oc] = s2x; sm2[w*COUT + oc + 1] = s2y;
            if (POOL) {
                pmx[w*COUT + oc] = mxx; pmx[w*COUT + oc + 1] = mxy;
                pmn[w*COUT + oc] = mnx; pmn[w*COUT + oc + 1] = mny;
            }
        }
    }
    __syncthreads();
    for (int e = tid; e < COUT; e += 256) {
        float a = 0.f, b2 = 0.f;
#pragma unroll
        for (int wi = 0; wi < 8; wi++) { a += sm1[wi*COUT + e]; b2 += sm2[wi*COUT + e]; }
        ps [(size_t)e*nblk + blockIdx.x] = a;
        ps2[(size_t)e*nblk + blockIdx.x] = b2;
    }
    if (POOL) {
        constexpr int NGR = 128/KP, WPG = KP/16;
        for (int e = tid; e < COUT*NGR; e += 256) {
            int g = e / COUT, oc = e - g*COUT;
            float mx = -1e30f, mn = 1e30f;
#pragma unroll
            for (int wi = 0; wi < WPG; wi++) {
                mx = fmaxf(mx, pmx[(g*WPG + wi)*COUT + oc]);
                mn = fminf(mn, pmn[(g*WPG + wi)*COUT + oc]);
            }
            int gg = pblock/KP + g;
            pmax[(size_t)oc*GCOUNT + gg] = mx;
            pmin[(size_t)oc*GCOUNT + gg] = mn;
        }
    }
}

// ---------------- finalize BN ----------------
__global__ __launch_bounds__(256) void finalize_kernel(const float* __restrict__ ps,
    const float* __restrict__ ps2, int nblk, float invP,
    const float* __restrict__ gamma, const float* __restrict__ beta,
    float* __restrict__ s, float* __restrict__ t)
{
    int c = blockIdx.x;
    float a = 0.f, b = 0.f;
    for (int i = threadIdx.x; i < nblk; i += 256) {
        a += ps [(size_t)c*nblk + i];
        b += ps2[(size_t)c*nblk + i];
    }
#pragma unroll
    for (int off = 16; off > 0; off >>= 1) {
        a += __shfl_down_sync(0xffffffffu, a, off);
        b += __shfl_down_sync(0xffffffffu, b, off);
    }
    __shared__ float sa[8], sb[8];
    int lane = threadIdx.x & 31, w = threadIdx.x >> 5;
    if (lane == 0) { sa[w] = a; sb[w] = b; }
    __syncthreads();
    if (threadIdx.x < 8) {
        a = sa[threadIdx.x]; b = sb[threadIdx.x];
#pragma unroll
        for (int off = 4; off > 0; off >>= 1) {
            a += __shfl_down_sync(0xffu, a, off);
            b += __shfl_down_sync(0xffu, b, off);
        }
        if (threadIdx.x == 0) {
            float mu = a * invP;
            float var = b * invP - mu*mu;
            float sc = gamma[c] / sqrtf(var + 1e-5f);
            s[c] = sc;
            t[c] = beta[c] - mu * sc;
        }
    }
}

// ---------------- pool apply ----------------
__global__ __launch_bounds__(256) void pool_apply_kernel(const float* __restrict__ pmax,
    const float* __restrict__ pmin, const float* __restrict__ s, const float* __restrict__ t,
    float* __restrict__ out, int chbase)
{
    int gid = blockIdx.x*256 + threadIdx.x;
    int oc = gid >> 14, g = gid & 16383;
    float sc = s[oc], tc = t[oc];
    float v = (sc > 0.f) ? pmax[gid] : pmin[gid];
    float r = fmaxf(v*sc + tc, 0.f);
    out[OUT_OFS + ((size_t)((g >> 10)*256 + chbase + oc))*MM + (g & 1023)] = r;
}

// ---------------- host ----------------
extern "C" void kernel_launch(void* const* d_in, const int* in_sizes, int n_in,
                              void* d_out, int out_size)
{
    const float* pc   = (const float*)d_in[0];
    const float* feat = (const float*)d_in[1];
    const float *bp[6], *gp[6], *bep[6];
    WPtrs wargs;
    for (int i = 0; i < 6; i++) {
        wargs.w[i] = (const float*)d_in[2 + 4*i];
        bp[i]  = (const float*)d_in[3 + 4*i];
        gp[i]  = (const float*)d_in[4 + 4*i];
        bep[i] = (const float*)d_in[5 + 4*i];
    }
    float* out = (float*)d_out;

    int *samp, *idx0, *idx1;
    float *bufA, *bufB, *ft, *sv, *tv, *ps, *ps2, *pmax, *pmin;
    uint16_t *wth, *wtl;
    cudaGetSymbolAddress((void**)&samp, g_samp);
    cudaGetSymbolAddress((void**)&idx0, g_idx0);
    cudaGetSymbolAddress((void**)&idx1, g_idx1);
    cudaGetSymbolAddress((void**)&bufA, g_bufA);
    cudaGetSymbolAddress((void**)&bufB, g_bufB);
    cudaGetSymbolAddress((void**)&ft,   g_ft);
    cudaGetSymbolAddress((void**)&sv,   g_s);
    cudaGetSymbolAddress((void**)&tv,   g_t);
    cudaGetSymbolAddress((void**)&ps,   g_ps);
    cudaGetSymbolAddress((void**)&ps2,  g_ps2);
    cudaGetSymbolAddress((void**)&pmax, g_pmax);
    cudaGetSymbolAddress((void**)&pmin, g_pmin);
    cudaGetSymbolAddress((void**)&wth,  g_wth);
    cudaGetSymbolAddress((void**)&wtl,  g_wtl);

    // smem: 24576 (X) + 2*COUT*WSTR (W) + 3072 (misc) + 32*COUT*4 (stats/pool)
    const int sm_g   = 24576 + 2*64*176  + 3072 + 32*64*4;
    const int sm_64  = 24576 + 2*64*144  + 3072 + 32*64*4;
    const int sm_96  = 24576 + 2*96*144  + 3072 + 32*96*4;
    const int sm_p64 = 24576 + 2*128*144 + 3072 + 32*128*4;
    const int sm_p96 = 24576 + 2*128*208 + 3072 + 32*128*4;
    cudaFuncSetAttribute(conv_mma<true,false,64,80,32>,   cudaFuncAttributeMaxDynamicSharedMemorySize, sm_g);
    cudaFuncSetAttribute(conv_mma<false,false,64,64,32>,  cudaFuncAttributeMaxDynamicSharedMemorySize, sm_64);
    cudaFuncSetAttribute(conv_mma<false,false,96,64,32>,  cudaFuncAttributeMaxDynamicSharedMemorySize, sm_96);
    cudaFuncSetAttribute(conv_mma<false,true,128,64,32>,  cudaFuncAttributeMaxDynamicSharedMemorySize, sm_p64);
    cudaFuncSetAttribute(conv_mma<false,true,128,96,64>,  cudaFuncAttributeMaxDynamicSharedMemorySize, sm_p96);

    wtr_kernel<<<6, 256>>>(wargs, wth, wtl);
    ftr_kernel<<<dim3(128, 2, BB), dim3(32, 8)>>>(feat, ft);
    fps_kernel<<<BB, 512>>>(pc, samp, out);
    ballquery2_kernel<<<dim3(BB,32), 256, 3*NN*sizeof(float)>>>(pc, samp, idx0, idx1, 0.01f, 0.04f);

    const int nb0 = P0/128, nb1 = P1/128;

    // branch 0: 67->64->64->128, K=32
    conv_mma<true,false,64,80,32><<<nb0, 256, sm_g>>>(nullptr, wth+0*12288, wtl+0*12288, bp[0],
        nullptr, nullptr, bufA, ps, ps2, nullptr, nullptr, pc, ft, out, idx0, 15, 5);
    finalize_kernel<<<64, 256>>>(ps, ps2, nb0, 1.f/P0, gp[0], bep[0], sv, tv);
    conv_mma<false,false,64,64,32><<<nb0, 256, sm_64>>>(bufA, wth+1*12288, wtl+1*12288, bp[1],
        sv, tv, bufB, ps, ps2, nullptr, nullptr, nullptr, nullptr, nullptr, nullptr, 0, 0);
    finalize_kernel<<<64, 256>>>(ps, ps2, nb0, 1.f/P0, gp[1], bep[1], sv, tv);
    conv_mma<false,true,128,64,32><<<nb0, 256, sm_p64>>>(bufB, wth+2*12288, wtl+2*12288, bp[2],
        sv, tv, nullptr, ps, ps2, pmax, pmin, nullptr, nullptr, nullptr, nullptr, 0, 0);
    finalize_kernel<<<128, 256>>>(ps, ps2, nb0, 1.f/P0, gp[2], bep[2], sv, tv);
    pool_apply_kernel<<<(128*GCOUNT)/256, 256>>>(pmax, pmin, sv, tv, out, 0);

    // branch 1: 67->64->96->128, K=64
    conv_mma<true,false,64,80,32><<<nb1, 256, sm_g>>>(nullptr, wth+3*12288, wtl+3*12288, bp[3],
        nullptr, nullptr, bufA, ps, ps2, nullptr, nullptr, pc, ft, out, idx1, 16, 6);
    finalize_kernel<<<64, 256>>>(ps, ps2, nb1, 1.f/P1, gp[3], bep[3], sv, tv);
    conv_mma<false,false,96,64,32><<<nb1, 256, sm_96>>>(bufA, wth+4*12288, wtl+4*12288, bp[4],
        sv, tv, bufB, ps, ps2, nullptr, nullptr, nullptr, nullptr, nullptr, nullptr, 0, 0);
    finalize_kernel<<<96, 256>>>(ps, ps2, nb1, 1.f/P1, gp[4], bep[4], sv, tv);
    conv_mma<false,true,128,96,64><<<nb1, 256, sm_p96>>>(bufB, wth+5*12288, wtl+5*12288, bp[5],
        sv, tv, nullptr, ps, ps2, pmax, pmin, nullptr, nullptr, nullptr, nullptr, 0, 0);
    finalize_kernel<<<128, 256>>>(ps, ps2, nb1, 1.f/P1, gp[5], bep[5], sv, tv);
    pool_apply_kernel<<<(128*GCOUNT)/256, 256>>>(pmax, pmin, sv, tv, out, 128);
}

// round 9
// speedup vs baseline: 1.2440x; 1.1615x over previous
#include <cuda_runtime.h>
#include <cstdint>

#define BB 16
#define NN 4096
#define MM 1024
#define P0 (BB*MM*32)
#define P1 (BB*MM*64)
#define OUT_OFS (BB*3*MM)
#define GCOUNT (BB*MM)

__device__ int      g_samp[BB*MM];
__device__ int      g_idx0[P0];
__device__ int      g_idx1[P1];
__device__ float    g_bufA[64*P1];
__device__ float    g_bufB[96*P1];
__device__ float    g_ft[BB*NN*64];
__device__ float    g_s[128];
__device__ float    g_t[128];
__device__ float    g_ps [128*8192];
__device__ float    g_ps2[128*8192];
__device__ float    g_pmax[128*GCOUNT];
__device__ float    g_pmin[128*GCOUNT];
__device__ uint16_t g_wth[6*12288];
__device__ uint16_t g_wtl[6*12288];

struct WPtrs { const float* w[6]; };

__device__ __forceinline__ uint32_t smem_u32(const void* p) {
    uint32_t a;
    asm("{ .reg .u64 t; cvta.to.shared.u64 t, %1; cvt.u32.u64 %0, t; }" : "=r"(a) : "l"(p));
    return a;
}
__device__ __forceinline__ uint32_t packbf(float hi, float lo) {
    uint32_t d;
    asm("cvt.rn.bf16x2.f32 %0, %1, %2;" : "=r"(d) : "f"(hi), "f"(lo));
    return d;
}
#define LDSMX4(r, addr) \
    asm volatile("ldmatrix.sync.aligned.m8n8.x4.shared.b16 {%0,%1,%2,%3}, [%4];" \
        : "=r"((r)[0]), "=r"((r)[1]), "=r"((r)[2]), "=r"((r)[3]) : "r"(addr))
#define MMABF(c, a, b0v, b1v) \
    asm volatile("mma.sync.aligned.m16n8k16.row.col.f32.bf16.bf16.f32 " \
        "{%0,%1,%2,%3}, {%4,%5,%6,%7}, {%8,%9}, {%0,%1,%2,%3};" \
        : "+f"((c)[0]), "+f"((c)[1]), "+f"((c)[2]), "+f"((c)[3]) \
        : "r"((a)[0]), "r"((a)[1]), "r"((a)[2]), "r"((a)[3]), "r"(b0v), "r"(b1v))

// ---------------- weights: permute + bf16 hi/lo split, [l][out][cpad] ----------------
__global__ void wtr_kernel(WPtrs wp, uint16_t* __restrict__ wth, uint16_t* __restrict__ wtl)
{
    const int cins[6]  = {67, 64, 64, 67, 64, 96};
    const int cpads[6] = {80, 64, 64, 80, 64, 96};
    const int couts[6] = {64, 64, 128, 64, 96, 128};
    const int gat[6]   = {1, 0, 0, 1, 0, 0};
    int l = blockIdx.x;
    const float* W = wp.w[l];
    int cin = cins[l], cpad = cpads[l], cout = couts[l];
    for (int e = threadIdx.x; e < cout*cpad; e += 256) {
        int o = e / cpad, c = e - o*cpad;
        int src;
        if (gat[l]) src = (c < 64) ? c + 3 : (c < 67 ? c - 64 : -1);
        else        src = (c < cin) ? c : -1;
        float wf = (src >= 0) ? W[o*cin + src] : 0.0f;
        uint16_t h = (uint16_t)(packbf(wf, 0.0f) >> 16);
        float hf = __uint_as_float((uint32_t)h << 16);
        wth[l*12288 + e] = h;
        wtl[l*12288 + e] = (uint16_t)(packbf(wf - hf, 0.0f) >> 16);
    }
}

// ---------------- feature transpose ----------------
__global__ __launch_bounds__(256) void ftr_kernel(const float* __restrict__ feat,
                                                  float* __restrict__ ft)
{
    __shared__ float tile[32][33];
    int b = blockIdx.z, c0 = blockIdx.y*32, n0 = blockIdx.x*32;
    int tx = threadIdx.x, ty = threadIdx.y;
#pragma unroll
    for (int k = 0; k < 4; k++)
        tile[ty + k*8][tx] = feat[(size_t)(b*64 + c0 + ty + k*8)*NN + n0 + tx];
    __syncthreads();
#pragma unroll
    for (int k = 0; k < 4; k++)
        ft[((size_t)b*NN + n0 + ty + k*8)*64 + c0 + tx] = tile[tx][ty + k*8];
}

// ---------------- FPS: single barrier per iteration ----------------
__global__ __launch_bounds__(512) void fps_kernel(const float* __restrict__ pc,
                                                  int* __restrict__ samp,
                                                  float* __restrict__ dout)
{
    int b = blockIdx.x, tid = threadIdx.x;
    const float* px = pc + (size_t)b*3*NN;
    const float* py = px + NN;
    const float* pz = py + NN;
    float x[8], yv[8], z[8], dmin[8];
#pragma unroll
    for (int j = 0; j < 8; j++) {
        int i = tid + j*512;
        x[j] = px[i]; yv[j] = py[i]; z[j] = pz[i]; dmin[j] = 1e10f;
    }
    __shared__ unsigned svu[2][16], siu[2][16];
    int lane = tid & 31, w = tid >> 5, far = 0;
    for (int it = 0; it < MM; it++) {
        int buf = it & 1;
        if (tid == 0) {
            samp[b*MM + it] = far;
            dout[(b*3+0)*MM + it] = px[far];
            dout[(b*3+1)*MM + it] = py[far];
            dout[(b*3+2)*MM + it] = pz[far];
        }
        float cx = px[far], cy = py[far], cz = pz[far];
        float bv = -1.0f; int bi = 0;
#pragma unroll
        for (int j = 0; j < 8; j++) {
            float dx = x[j]-cx, dy = yv[j]-cy, dz = z[j]-cz;
            float d = __fadd_rn(__fadd_rn(__fmul_rn(dx,dx), __fmul_rn(dy,dy)), __fmul_rn(dz,dz));
            float nd = fminf(dmin[j], d);
            dmin[j] = nd;
            if (nd > bv) { bv = nd; bi = tid + j*512; }
        }
        unsigned fb = __float_as_uint(bv);
        unsigned mw = __reduce_max_sync(0xffffffffu, fb);
        unsigned mi = __reduce_min_sync(0xffffffffu, (fb == mw) ? (unsigned)bi : 0xffffffffu);
        if (lane == 0) { svu[buf][w] = mw; siu[buf][w] = mi; }
        __syncthreads();
        unsigned f2 = (lane < 16) ? svu[buf][lane] : 0u;
        unsigned i2 = (lane < 16) ? siu[buf][lane] : 0xffffffffu;
        unsigned m2 = __reduce_max_sync(0xffffffffu, f2);
        far = (int)__reduce_min_sync(0xffffffffu, (f2 == m2) ? i2 : 0xffffffffu);
    }
}

// ---------------- dual-radius ball query ----------------
__global__ __launch_bounds__(256) void ballquery2_kernel(const float* __restrict__ pc,
    const int* __restrict__ samp, int* __restrict__ gidx0, int* __restrict__ gidx1,
    float r2a, float r2b)
{
    extern __shared__ float sh[];
    float* sx = sh; float* sy = sh + NN; float* sz = sh + 2*NN;
    int b = blockIdx.x;
    const float* px = pc + (size_t)b*3*NN;
    for (int i = threadIdx.x; i < NN; i += blockDim.x) {
        sx[i] = px[i]; sy[i] = px[NN+i]; sz[i] = px[2*NN+i];
    }
    __syncthreads();
    int lane = threadIdx.x & 31, wid = threadIdx.x >> 5;
    int mstart = blockIdx.y * 32;
    unsigned lt = (1u << lane) - 1u;
    for (int m = mstart + wid; m < mstart + 32; m += 8) {
        int ci = samp[b*MM + m];
        float cx = sx[ci], cy = sy[ci], cz = sz[ci];
        int cnt0 = 0, cnt1 = 0, f0 = -1, f1 = -1;
        int* out0 = gidx0 + ((size_t)(b*MM + m))*32;
        int* out1 = gidx1 + ((size_t)(b*MM + m))*64;
        for (int base = 0; base < NN && (cnt0 < 32 || cnt1 < 64); base += 32) {
            int i = base + lane;
            float dx = sx[i]-cx, dy = sy[i]-cy, dz = sz[i]-cz;
            float d = __fadd_rn(__fadd_rn(__fmul_rn(dx,dx), __fmul_rn(dy,dy)), __fmul_rn(dz,dz));
            bool ok0 = d < r2a, ok1 = d < r2b;
            unsigned m0 = __ballot_sync(0xffffffffu, ok0);
            unsigned m1 = __ballot_sync(0xffffffffu, ok1);
            if (f0 < 0 && m0) f0 = base + __ffs(m0) - 1;
            if (f1 < 0 && m1) f1 = base + __ffs(m1) - 1;
            int p0 = cnt0 + __popc(m0 & lt);
            int p1 = cnt1 + __popc(m1 & lt);
            if (ok0 && p0 < 32) out0[p0] = i;
            if (ok1 && p1 < 64) out1[p1] = i;
            cnt0 = min(32, cnt0 + __popc(m0));
            cnt1 = min(64, cnt1 + __popc(m1));
        }
        for (int p = cnt0 + lane; p < 32; p += 32) out0[p] = f0;
        for (int p = cnt1 + lane; p < 64; p += 32) out1[p] = f1;
    }
}

// ---------------- tensor-core conv: 256 pos x COUTB per block, bf16 3-term ----------------
template<bool GATHER, bool POOL, int COUTB, int CPAD, int KP>
__global__ __launch_bounds__(256, 2) void conv_mma(
    const float* __restrict__ xin,
    const uint16_t* __restrict__ Whi, const uint16_t* __restrict__ Wlo,
    const float* __restrict__ bias,
    const float* __restrict__ bns, const float* __restrict__ bnt,
    float* __restrict__ y, float* __restrict__ ps, float* __restrict__ ps2,
    float* __restrict__ pmax, float* __restrict__ pmin,
    int cstride,
    const float* __restrict__ pc, const float* __restrict__ ft,
    const float* __restrict__ newpc, const int* __restrict__ gidx,
    int mkshift, int kshift)
{
    constexpr int NK = CPAD/16;
    constexpr int WSTR = CPAD*2 + 16;
    constexpr int XROW = 48, XPLANE = 256*XROW;
    constexpr int WOFF = 4*XPLANE;                 // 49152
    constexpr int MOFF = WOFF + 2*COUTB*WSTR;

    extern __shared__ __align__(16) unsigned char smem[];
    float* ssA = (float*)(smem + MOFF);
    float* stA = (float*)(smem + MOFF + 512);
    unsigned* sfb = (unsigned*)(smem + MOFF + 1024);
    float* sdx = (float*)(smem + MOFF + 2048);
    float* sdy = (float*)(smem + MOFF + 3072);
    float* sdz = (float*)(smem + MOFF + 4096);
    float* sm1 = (float*)(smem + MOFF + 5120);
    float* sm2 = sm1 + 8*COUTB;
    float* pmx = sm2 + 8*COUTB;
    float* pmn = pmx + 8*COUTB;

    const int tid = threadIdx.x, lane = tid & 31, w = tid >> 5;
    const int pblock = blockIdx.x * 256;
    const int ocbase = blockIdx.y * COUTB;
    const int nblk = gridDim.x;
    const uint16_t* Whi_b = Whi + (size_t)ocbase*CPAD;
    const uint16_t* Wlo_b = Wlo + (size_t)ocbase*CPAD;

    if (GATHER) {
        int p = pblock + tid;
        int bbv = p >> mkshift, mmv = (p >> kshift) & (MM-1);
        int ix = gidx[p];
        sfb[tid] = (unsigned)((bbv*NN + ix) * 64);
        sdx[tid] = pc[(size_t)(bbv*3+0)*NN+ix] - newpc[(size_t)(bbv*3+0)*MM+mmv];
        sdy[tid] = pc[(size_t)(bbv*3+1)*NN+ix] - newpc[(size_t)(bbv*3+1)*MM+mmv];
        sdz[tid] = pc[(size_t)(bbv*3+2)*NN+ix] - newpc[(size_t)(bbv*3+2)*MM+mmv];
    } else {
        if (tid < CPAD) { ssA[tid] = bns[tid]; stA[tid] = bnt[tid]; }
    }
    for (int e = tid; e < COUTB*CPAD/2; e += 256) {
        int o = e / (CPAD/2), cp = e - o*(CPAD/2);
        *(uint32_t*)(smem + WOFF + o*WSTR + cp*4) = ((const uint32_t*)Whi_b)[e];
        *(uint32_t*)(smem + WOFF + COUTB*WSTR + o*WSTR + cp*4) = ((const uint32_t*)Wlo_b)[e];
    }
    __syncthreads();

    float4 xr[4];
    auto stage_load = [&](int kc) {
#pragma unroll
        for (int i = 0; i < 4; i++) {
            int e = tid + i*256, pos = e >> 2, c4 = e & 3;
            if (GATHER) {
                if (kc < 4) xr[i] = *(const float4*)&ft[sfb[pos] + kc*16 + c4*4];
                else xr[i] = (c4 == 0) ? make_float4(sdx[pos], sdy[pos], sdz[pos], 0.f)
                                       : make_float4(0.f, 0.f, 0.f, 0.f);
            } else {
                xr[i] = *(const float4*)&xin[(size_t)(pblock+pos)*CPAD + kc*16 + c4*4];
            }
        }
    };
    auto stage_conv = [&](int kc, int buf) {
        unsigned char* xh = smem + (buf*2+0)*XPLANE;
        unsigned char* xl = smem + (buf*2+1)*XPLANE;
#pragma unroll
        for (int i = 0; i < 4; i++) {
            int e = tid + i*256, pos = e >> 2, c4 = e & 3;
            float4 v = xr[i];
            if (!GATHER) {
                int c0 = kc*16 + c4*4;
                float4 sc = *(float4*)&ssA[c0];
                float4 tc = *(float4*)&stA[c0];
                v.x = fmaxf(v.x*sc.x+tc.x, 0.f); v.y = fmaxf(v.y*sc.y+tc.y, 0.f);
                v.z = fmaxf(v.z*sc.z+tc.z, 0.f); v.w = fmaxf(v.w*sc.w+tc.w, 0.f);
            }
            uint32_t h0 = packbf(v.y, v.x), h1 = packbf(v.w, v.z);
            float rx = __uint_as_float(h0 << 16), ry = __uint_as_float(h0 & 0xffff0000u);
            float rz = __uint_as_float(h1 << 16), rw = __uint_as_float(h1 & 0xffff0000u);
            uint32_t off = pos*XROW + c4*8;
            *(uint2*)(xh + off) = make_uint2(h0, h1);
            *(uint2*)(xl + off) = make_uint2(packbf(v.y-ry, v.x-rx), packbf(v.w-rw, v.z-rz));
        }
    };

    const uint32_t base = smem_u32(smem);
    const uint32_t aoff = base + (uint32_t)((w*32 + (lane & 15))*XROW + (lane >> 4)*16);
    const uint32_t boff = base + WOFF +
        (uint32_t)((((lane >> 4) & 1)*8 + (lane & 7))*WSTR + ((lane >> 3) & 1)*16);

    float acc[2][COUTB/8][4];
#pragma unroll
    for (int t = 0; t < 2; t++)
#pragma unroll
        for (int n = 0; n < COUTB/8; n++)
#pragma unroll
            for (int c = 0; c < 4; c++) acc[t][n][c] = 0.f;

    stage_load(0); stage_conv(0, 0);
    __syncthreads();

    for (int kc = 0; kc < NK; kc++) {
        int buf = kc & 1;
        if (kc + 1 < NK) stage_load(kc + 1);
        uint32_t ah[2][4], al[2][4];
#pragma unroll
        for (int t = 0; t < 2; t++) {
            LDSMX4(ah[t], aoff + t*16*XROW + (buf*2+0)*XPLANE);
            LDSMX4(al[t], aoff + t*16*XROW + (buf*2+1)*XPLANE);
        }
#pragma unroll
        for (int j = 0; j < COUTB/16; j++) {
            uint32_t bh[4], bl[4];
            LDSMX4(bh, boff + j*16*WSTR + kc*32);
            LDSMX4(bl, boff + COUTB*WSTR + j*16*WSTR + kc*32);
#pragma unroll
            for (int t = 0; t < 2; t++) {
                MMABF(acc[t][2*j],   ah[t], bh[0], bh[1]);
                MMABF(acc[t][2*j+1], ah[t], bh[2], bh[3]);
                MMABF(acc[t][2*j],   ah[t], bl[0], bl[1]);
                MMABF(acc[t][2*j+1], ah[t], bl[2], bl[3]);
                MMABF(acc[t][2*j],   al[t], bh[0], bh[1]);
                MMABF(acc[t][2*j+1], al[t], bh[2], bh[3]);
            }
        }
        if (kc + 1 < NK) stage_conv(kc + 1, buf ^ 1);
        __syncthreads();
    }

    const int q = lane >> 2, r2i = (lane & 3)*2;
#pragma unroll
    for (int nt = 0; nt < COUTB/8; nt++) {
        int ocl = nt*8 + r2i;
        int oc  = ocbase + ocl;
        float2 bv = *(const float2*)&bias[oc];
        float s1x = 0.f, s1y = 0.f, s2x = 0.f, s2y = 0.f;
        float mxx = -1e30f, mxy = -1e30f, mnx = 1e30f, mny = 1e30f;
#pragma unroll
        for (int t = 0; t < 2; t++) {
            float2 c01 = make_float2(acc[t][nt][0]+bv.x, acc[t][nt][1]+bv.y);
            float2 c23 = make_float2(acc[t][nt][2]+bv.x, acc[t][nt][3]+bv.y);
            if (!POOL) {
                *(float2*)&y[(size_t)(pblock + w*32 + t*16 + q)*cstride + oc]     = c01;
                *(float2*)&y[(size_t)(pblock + w*32 + t*16 + q + 8)*cstride + oc] = c23;
            }
            s1x += c01.x + c23.x;  s1y += c01.y + c23.y;
            s2x += c01.x*c01.x + c23.x*c23.x;
            s2y += c01.y*c01.y + c23.y*c23.y;
            mxx = fmaxf(mxx, fmaxf(c01.x, c23.x)); mxy = fmaxf(mxy, fmaxf(c01.y, c23.y));
            mnx = fminf(mnx, fminf(c01.x, c23.x)); mny = fminf(mny, fminf(c01.y, c23.y));
        }
#pragma unroll
        for (int o2 = 4; o2 <= 16; o2 <<= 1) {
            s1x += __shfl_xor_sync(0xffffffffu, s1x, o2);
            s1y += __shfl_xor_sync(0xffffffffu, s1y, o2);
            s2x += __shfl_xor_sync(0xffffffffu, s2x, o2);
            s2y += __shfl_xor_sync(0xffffffffu, s2y, o2);
            if (POOL) {
                mxx = fmaxf(mxx, __shfl_xor_sync(0xffffffffu, mxx, o2));
                mxy = fmaxf(mxy, __shfl_xor_sync(0xffffffffu, mxy, o2));
                mnx = fminf(mnx, __shfl_xor_sync(0xffffffffu, mnx, o2));
                mny = fminf(mny, __shfl_xor_sync(0xffffffffu, mny, o2));
            }
        }
        if (q == 0) {
            sm1[w*COUTB + ocl] = s1x; sm1[w*COUTB + ocl + 1] = s1y;
            sm2[w*COUTB + ocl] = s2x; sm2[w*COUTB + ocl + 1] = s2y;
            if (POOL) {
                if (KP == 32) {   // one warp == one group
                    size_t g = (size_t)(pblock >> 5) + w;
                    pmax[(size_t)oc*GCOUNT + g] = mxx; pmax[(size_t)(oc+1)*GCOUNT + g] = mxy;
                    pmin[(size_t)oc*GCOUNT + g] = mnx; pmin[(size_t)(oc+1)*GCOUNT + g] = mny;
                } else {
                    pmx[w*COUTB + ocl] = mxx; pmx[w*COUTB + ocl + 1] = mxy;
                    pmn[w*COUTB + ocl] = mnx; pmn[w*COUTB + ocl + 1] = mny;
                }
            }
        }
    }
    __syncthreads();
    for (int e = tid; e < COUTB; e += 256) {
        float a = 0.f, b2 = 0.f;
#pragma unroll
        for (int wi = 0; wi < 8; wi++) { a += sm1[wi*COUTB + e]; b2 += sm2[wi*COUTB + e]; }
        ps [(size_t)(ocbase + e)*nblk + blockIdx.x] = a;
        ps2[(size_t)(ocbase + e)*nblk + blockIdx.x] = b2;
    }
    if (POOL && KP == 64) {
        for (int e = tid; e < COUTB*4; e += 256) {   // 4 groups of 64 per block
            int g = e / COUTB, ocl = e - g*COUTB;
            float mx = fmaxf(pmx[(g*2)*COUTB + ocl], pmx[(g*2+1)*COUTB + ocl]);
            float mn = fminf(pmn[(g*2)*COUTB + ocl], pmn[(g*2+1)*COUTB + ocl]);
            size_t gg = (size_t)(pblock >> 6) + g;
            pmax[(size_t)(ocbase + ocl)*GCOUNT + gg] = mx;
            pmin[(size_t)(ocbase + ocl)*GCOUNT + gg] = mn;
        }
    }
}

// ---------------- finalize BN ----------------
__global__ __launch_bounds__(256) void finalize_kernel(const float* __restrict__ ps,
    const float* __restrict__ ps2, int nblk, float invP,
    const float* __restrict__ gamma, const float* __restrict__ beta,
    float* __restrict__ s, float* __restrict__ t)
{
    int c = blockIdx.x;
    float a = 0.f, b = 0.f;
    for (int i = threadIdx.x; i < nblk; i += 256) {
        a += ps [(size_t)c*nblk + i];
        b += ps2[(size_t)c*nblk + i];
    }
#pragma unroll
    for (int off = 16; off > 0; off >>= 1) {
        a += __shfl_down_sync(0xffffffffu, a, off);
        b += __shfl_down_sync(0xffffffffu, b, off);
    }
    __shared__ float sa[8], sb[8];
    int lane = threadIdx.x & 31, w = threadIdx.x >> 5;
    if (lane == 0) { sa[w] = a; sb[w] = b; }
    __syncthreads();
    if (threadIdx.x < 8) {
        a = sa[threadIdx.x]; b = sb[threadIdx.x];
#pragma unroll
        for (int off = 4; off > 0; off >>= 1) {
            a += __shfl_down_sync(0xffu, a, off);
            b += __shfl_down_sync(0xffu, b, off);
        }
        if (threadIdx.x == 0) {
            float mu = a * invP;
            float var = b * invP - mu*mu;
            float sc = gamma[c] / sqrtf(var + 1e-5f);
            s[c] = sc;
            t[c] = beta[c] - mu * sc;
        }
    }
}

// ---------------- pool apply ----------------
__global__ __launch_bounds__(256) void pool_apply_kernel(const float* __restrict__ pmax,
    const float* __restrict__ pmin, const float* __restrict__ s, const float* __restrict__ t,
    float* __restrict__ out, int chbase)
{
    int gid = blockIdx.x*256 + threadIdx.x;
    int oc = gid >> 14, g = gid & 16383;
    float sc = s[oc], tc = t[oc];
    float v = (sc > 0.f) ? pmax[gid] : pmin[gid];
    float r = fmaxf(v*sc + tc, 0.f);
    out[OUT_OFS + ((size_t)((g >> 10)*256 + chbase + oc))*MM + (g & 1023)] = r;
}

// ---------------- host ----------------
extern "C" void kernel_launch(void* const* d_in, const int* in_sizes, int n_in,
                              void* d_out, int out_size)
{
    const float* pc   = (const float*)d_in[0];
    const float* feat = (const float*)d_in[1];
    const float *bp[6], *gp[6], *bep[6];
    WPtrs wargs;
    for (int i = 0; i < 6; i++) {
        wargs.w[i] = (const float*)d_in[2 + 4*i];
        bp[i]  = (const float*)d_in[3 + 4*i];
        gp[i]  = (const float*)d_in[4 + 4*i];
        bep[i] = (const float*)d_in[5 + 4*i];
    }
    float* out = (float*)d_out;

    int *samp, *idx0, *idx1;
    float *bufA, *bufB, *ft, *sv, *tv, *ps, *ps2, *pmax, *pmin;
    uint16_t *wth, *wtl;
    cudaGetSymbolAddress((void**)&samp, g_samp);
    cudaGetSymbolAddress((void**)&idx0, g_idx0);
    cudaGetSymbolAddress((void**)&idx1, g_idx1);
    cudaGetSymbolAddress((void**)&bufA, g_bufA);
    cudaGetSymbolAddress((void**)&bufB, g_bufB);
    cudaGetSymbolAddress((void**)&ft,   g_ft);
    cudaGetSymbolAddress((void**)&sv,   g_s);
    cudaGetSymbolAddress((void**)&tv,   g_t);
    cudaGetSymbolAddress((void**)&ps,   g_ps);
    cudaGetSymbolAddress((void**)&ps2,  g_ps2);
    cudaGetSymbolAddress((void**)&pmax, g_pmax);
    cudaGetSymbolAddress((void**)&pmin, g_pmin);
    cudaGetSymbolAddress((void**)&wth,  g_wth);
    cudaGetSymbolAddress((void**)&wtl,  g_wtl);

    // smem per instantiation: WOFF(49152) + 2*COUTB*WSTR + 5120 + 32*COUTB*4
    const int sm_A = 49152 + 2*64*176 + 5120 + 8192;   // gather 64x80   = 84992
    const int sm_B = 49152 + 2*64*144 + 5120 + 8192;   // 64x64          = 80896
    const int sm_C = sm_B;                              // pool 64x64 KP32
    const int sm_D = 49152 + 2*48*144 + 5120 + 6144;   // 48x64          = 74240
    const int sm_E = 49152 + 2*64*208 + 5120 + 8192;   // pool 64x96 KP64= 89088
    cudaFuncSetAttribute(conv_mma<true,false,64,80,32>,  cudaFuncAttributeMaxDynamicSharedMemorySize, sm_A);
    cudaFuncSetAttribute(conv_mma<false,false,64,64,32>, cudaFuncAttributeMaxDynamicSharedMemorySize, sm_B);
    cudaFuncSetAttribute(conv_mma<false,true,64,64,32>,  cudaFuncAttributeMaxDynamicSharedMemorySize, sm_C);
    cudaFuncSetAttribute(conv_mma<false,false,48,64,32>, cudaFuncAttributeMaxDynamicSharedMemorySize, sm_D);
    cudaFuncSetAttribute(conv_mma<false,true,64,96,64>,  cudaFuncAttributeMaxDynamicSharedMemorySize, sm_E);

    wtr_kernel<<<6, 256>>>(wargs, wth, wtl);
    ftr_kernel<<<dim3(128, 2, BB), dim3(32, 8)>>>(feat, ft);
    fps_kernel<<<BB, 512>>>(pc, samp, out);
    ballquery2_kernel<<<dim3(BB,32), 256, 3*NN*sizeof(float)>>>(pc, samp, idx0, idx1, 0.01f, 0.04f);

    const int nb0 = P0/256, nb1 = P1/256;

    // branch 0: 67->64->64->128, K=32
    conv_mma<true,false,64,80,32><<<dim3(nb0,1), 256, sm_A>>>(nullptr, wth+0*12288, wtl+0*12288,
        bp[0], nullptr, nullptr, bufA, ps, ps2, nullptr, nullptr, 64, pc, ft, out, idx0, 15, 5);
    finalize_kernel<<<64, 256>>>(ps, ps2, nb0, 1.f/P0, gp[0], bep[0], sv, tv);
    conv_mma<false,false,64,64,32><<<dim3(nb0,1), 256, sm_B>>>(bufA, wth+1*12288, wtl+1*12288,
        bp[1], sv, tv, bufB, ps, ps2, nullptr, nullptr, 64, nullptr, nullptr, nullptr, nullptr, 0, 0);
    finalize_kernel<<<64, 256>>>(ps, ps2, nb0, 1.f/P0, gp[1], bep[1], sv, tv);
    conv_mma<false,true,64,64,32><<<dim3(nb0,2), 256, sm_C>>>(bufB, wth+2*12288, wtl+2*12288,
        bp[2], sv, tv, nullptr, ps, ps2, pmax, pmin, 128, nullptr, nullptr, nullptr, nullptr, 0, 0);
    finalize_kernel<<<128, 256>>>(ps, ps2, nb0, 1.f/P0, gp[2], bep[2], sv, tv);
    pool_apply_kernel<<<(128*GCOUNT)/256, 256>>>(pmax, pmin, sv, tv, out, 0);

    // branch 1: 67->64->96->128, K=64
    conv_mma<true,false,64,80,32><<<dim3(nb1,1), 256, sm_A>>>(nullptr, wth+3*12288, wtl+3*12288,
        bp[3], nullptr, nullptr, bufA, ps, ps2, nullptr, nullptr, 64, pc, ft, out, idx1, 16, 6);
    finalize_kernel<<<64, 256>>>(ps, ps2, nb1, 1.f/P1, gp[3], bep[3], sv, tv);
    conv_mma<false,false,48,64,32><<<dim3(nb1,2), 256, sm_D>>>(bufA, wth+4*12288, wtl+4*12288,
        bp[4], sv, tv, bufB, ps, ps2, nullptr, nullptr, 96, nullptr, nullptr, nullptr, nullptr, 0, 0);
    finalize_kernel<<<96, 256>>>(ps, ps2, nb1, 1.f/P1, gp[4], bep[4], sv, tv);
    conv_mma<false,true,64,96,64><<<dim3(nb1,2), 256, sm_E>>>(bufB, wth+5*12288, wtl+5*12288,
        bp[5], sv, tv, nullptr, ps, ps2, pmax, pmin, 128, nullptr, nullptr, nullptr, nullptr, 0, 0);
    finalize_kernel<<<128, 256>>>(ps, ps2, nb1, 1.f/P1, gp[5], bep[5], sv, tv);
    pool_apply_kernel<<<(128*GCOUNT)/256, 256>>>(pmax, pmin, sv, tv, out, 128);
}

// round 11
// speedup vs baseline: 1.3165x; 1.0583x over previous
#include <cuda_runtime.h>
#include <cuda_fp16.h>
#include <cstdint>

#define BB 16
#define NN 4096
#define MM 1024
#define P0 (BB*MM*32)
#define P1 (BB*MM*64)
#define OUT_OFS (BB*3*MM)
#define GCOUNT (BB*MM)

__device__ int      g_samp[BB*MM];
__device__ int      g_idx0[P0];
__device__ int      g_idx1[P1];
__device__ float    g_bufA[64*P1];
__device__ float    g_bufB[96*P1];
__device__ float    g_ft[BB*NN*64];
__device__ float    g_s[128];
__device__ float    g_t[128];
__device__ float    g_ps [128*8192];
__device__ float    g_ps2[128*8192];
__device__ float    g_pmax[128*GCOUNT];
__device__ float    g_pmin[128*GCOUNT];
__device__ uint16_t g_wth[6*12288];   // fp16 weights [l][out][cpad]

struct WPtrs { const float* w[6]; };

__device__ __forceinline__ uint32_t smem_u32(const void* p) {
    uint32_t a;
    asm("{ .reg .u64 t; cvta.to.shared.u64 t, %1; cvt.u32.u64 %0, t; }" : "=r"(a) : "l"(p));
    return a;
}
#define LDSMX4(r, addr) \
    asm volatile("ldmatrix.sync.aligned.m8n8.x4.shared.b16 {%0,%1,%2,%3}, [%4];" \
        : "=r"((r)[0]), "=r"((r)[1]), "=r"((r)[2]), "=r"((r)[3]) : "r"(addr))
#define MMAH(c, a, b0v, b1v) \
    asm volatile("mma.sync.aligned.m16n8k16.row.col.f32.f16.f16.f32 " \
        "{%0,%1,%2,%3}, {%4,%5,%6,%7}, {%8,%9}, {%0,%1,%2,%3};" \
        : "+f"((c)[0]), "+f"((c)[1]), "+f"((c)[2]), "+f"((c)[3]) \
        : "r"((a)[0]), "r"((a)[1]), "r"((a)[2]), "r"((a)[3]), "r"(b0v), "r"(b1v))

// ---------------- weights: permute + fp16, [l][out][cpad] ----------------
__global__ void wtr_kernel(WPtrs wp, uint16_t* __restrict__ wth)
{
    const int cins[6]  = {67, 64, 64, 67, 64, 96};
    const int cpads[6] = {80, 64, 64, 80, 64, 96};
    const int couts[6] = {64, 64, 128, 64, 96, 128};
    const int gat[6]   = {1, 0, 0, 1, 0, 0};
    int l = blockIdx.x;
    const float* W = wp.w[l];
    int cin = cins[l], cpad = cpads[l], cout = couts[l];
    for (int e = threadIdx.x; e < cout*cpad; e += 256) {
        int o = e / cpad, c = e - o*cpad;
        int src;
        if (gat[l]) src = (c < 64) ? c + 3 : (c < 67 ? c - 64 : -1);
        else        src = (c < cin) ? c : -1;
        float wf = (src >= 0) ? W[o*cin + src] : 0.0f;
        __half h = __float2half_rn(wf);
        wth[l*12288 + e] = *reinterpret_cast<uint16_t*>(&h);
    }
}

// ---------------- feature transpose ----------------
__global__ __launch_bounds__(256) void ftr_kernel(const float* __restrict__ feat,
                                                  float* __restrict__ ft)
{
    __shared__ float tile[32][33];
    int b = blockIdx.z, c0 = blockIdx.y*32, n0 = blockIdx.x*32;
    int tx = threadIdx.x, ty = threadIdx.y;
#pragma unroll
    for (int k = 0; k < 4; k++)
        tile[ty + k*8][tx] = feat[(size_t)(b*64 + c0 + ty + k*8)*NN + n0 + tx];
    __syncthreads();
#pragma unroll
    for (int k = 0; k < 4; k++)
        ft[((size_t)b*NN + n0 + ty + k*8)*64 + c0 + tx] = tile[tx][ty + k*8];
}

// ---------------- FPS ----------------
__global__ __launch_bounds__(512) void fps_kernel(const float* __restrict__ pc,
                                                  int* __restrict__ samp,
                                                  float* __restrict__ dout)
{
    int b = blockIdx.x, tid = threadIdx.x;
    const float* px = pc + (size_t)b*3*NN;
    const float* py = px + NN;
    const float* pz = py + NN;
    float x[8], yv[8], z[8], dmin[8];
#pragma unroll
    for (int j = 0; j < 8; j++) {
        int i = tid + j*512;
        x[j] = px[i]; yv[j] = py[i]; z[j] = pz[i]; dmin[j] = 1e10f;
    }
    __shared__ unsigned svu[2][16], siu[2][16];
    int lane = tid & 31, w = tid >> 5, far = 0;
    for (int it = 0; it < MM; it++) {
        int buf = it & 1;
        if (tid == 0) {
            samp[b*MM + it] = far;
            dout[(b*3+0)*MM + it] = px[far];
            dout[(b*3+1)*MM + it] = py[far];
            dout[(b*3+2)*MM + it] = pz[far];
        }
        float cx = px[far], cy = py[far], cz = pz[far];
        float bv = -1.0f; int bi = 0;
#pragma unroll
        for (int j = 0; j < 8; j++) {
            float dx = x[j]-cx, dy = yv[j]-cy, dz = z[j]-cz;
            float d = __fadd_rn(__fadd_rn(__fmul_rn(dx,dx), __fmul_rn(dy,dy)), __fmul_rn(dz,dz));
            float nd = fminf(dmin[j], d);
            dmin[j] = nd;
            if (nd > bv) { bv = nd; bi = tid + j*512; }
        }
        unsigned fb = __float_as_uint(bv);
        unsigned mw = __reduce_max_sync(0xffffffffu, fb);
        unsigned mi = __reduce_min_sync(0xffffffffu, (fb == mw) ? (unsigned)bi : 0xffffffffu);
        if (lane == 0) { svu[buf][w] = mw; siu[buf][w] = mi; }
        __syncthreads();
        unsigned f2 = (lane < 16) ? svu[buf][lane] : 0u;
        unsigned i2 = (lane < 16) ? siu[buf][lane] : 0xffffffffu;
        unsigned m2 = __reduce_max_sync(0xffffffffu, f2);
        far = (int)__reduce_min_sync(0xffffffffu, (f2 == m2) ? i2 : 0xffffffffu);
    }
}

// ---------------- dual-radius ball query ----------------
__global__ __launch_bounds__(256) void ballquery2_kernel(const float* __restrict__ pc,
    const int* __restrict__ samp, int* __restrict__ gidx0, int* __restrict__ gidx1,
    float r2a, float r2b)
{
    extern __shared__ float sh[];
    float* sx = sh; float* sy = sh + NN; float* sz = sh + 2*NN;
    int b = blockIdx.x;
    const float* px = pc + (size_t)b*3*NN;
    for (int i = threadIdx.x; i < NN; i += blockDim.x) {
        sx[i] = px[i]; sy[i] = px[NN+i]; sz[i] = px[2*NN+i];
    }
    __syncthreads();
    int lane = threadIdx.x & 31, wid = threadIdx.x >> 5;
    int mstart = blockIdx.y * 32;
    unsigned lt = (1u << lane) - 1u;
    for (int m = mstart + wid; m < mstart + 32; m += 8) {
        int ci = samp[b*MM + m];
        float cx = sx[ci], cy = sy[ci], cz = sz[ci];
        int cnt0 = 0, cnt1 = 0, f0 = -1, f1 = -1;
        int* out0 = gidx0 + ((size_t)(b*MM + m))*32;
        int* out1 = gidx1 + ((size_t)(b*MM + m))*64;
        for (int base = 0; base < NN && (cnt0 < 32 || cnt1 < 64); base += 32) {
            int i = base + lane;
            float dx = sx[i]-cx, dy = sy[i]-cy, dz = sz[i]-cz;
            float d = __fadd_rn(__fadd_rn(__fmul_rn(dx,dx), __fmul_rn(dy,dy)), __fmul_rn(dz,dz));
            bool ok0 = d < r2a, ok1 = d < r2b;
            unsigned m0 = __ballot_sync(0xffffffffu, ok0);
            unsigned m1 = __ballot_sync(0xffffffffu, ok1);
            if (f0 < 0 && m0) f0 = base + __ffs(m0) - 1;
            if (f1 < 0 && m1) f1 = base + __ffs(m1) - 1;
            int p0 = cnt0 + __popc(m0 & lt);
            int p1 = cnt1 + __popc(m1 & lt);
            if (ok0 && p0 < 32) out0[p0] = i;
            if (ok1 && p1 < 64) out1[p1] = i;
            cnt0 = min(32, cnt0 + __popc(m0));
            cnt1 = min(64, cnt1 + __popc(m1));
        }
        for (int p = cnt0 + lane; p < 32; p += 32) out0[p] = f0;
        for (int p = cnt1 + lane; p < 64; p += 32) out1[p] = f1;
    }
}

// ---------------- tensor-core conv: 256 pos x COUTB per block, fp16 2-term ----------------
template<bool GATHER, bool POOL, int COUTB, int CPAD, int KP>
__global__ __launch_bounds__(256, 2) void conv_mma(
    const float* __restrict__ xin,
    const uint16_t* __restrict__ Wh,
    const float* __restrict__ bias,
    const float* __restrict__ bns, const float* __restrict__ bnt,
    float* __restrict__ y, float* __restrict__ ps, float* __restrict__ ps2,
    float* __restrict__ pmax, float* __restrict__ pmin,
    int cstride,
    const float* __restrict__ pc, const float* __restrict__ ft,
    const float* __restrict__ newpc, const int* __restrict__ gidx,
    int mkshift, int kshift)
{
    constexpr int NK = CPAD/16;
    constexpr int WSTR = CPAD*2 + 16;
    constexpr int XROW = 48, XPLANE = 256*XROW;
    constexpr int WOFF = 4*XPLANE;                 // 49152
    constexpr int MOFF = WOFF + COUTB*WSTR;

    extern __shared__ __align__(16) unsigned char smem[];
    float* ssA = (float*)(smem + MOFF);
    float* stA = (float*)(smem + MOFF + 512);
    unsigned* sfb = (unsigned*)(smem + MOFF + 1024);
    float* sdx = (float*)(smem + MOFF + 2048);
    float* sdy = (float*)(smem + MOFF + 3072);
    float* sdz = (float*)(smem + MOFF + 4096);
    float* sm1 = (float*)(smem + MOFF + 5120);
    float* sm2 = sm1 + 8*COUTB;
    float* pmx = sm2 + 8*COUTB;
    float* pmn = pmx + 8*COUTB;

    const int tid = threadIdx.x, lane = tid & 31, w = tid >> 5;
    const int pblock = blockIdx.x * 256;
    const int ocbase = blockIdx.y * COUTB;
    const int nblk = gridDim.x;
    const uint16_t* Wh_b = Wh + (size_t)ocbase*CPAD;

    if (GATHER) {
        int p = pblock + tid;
        int bbv = p >> mkshift, mmv = (p >> kshift) & (MM-1);
        int ix = gidx[p];
        sfb[tid] = (unsigned)((bbv*NN + ix) * 64);
        sdx[tid] = pc[(size_t)(bbv*3+0)*NN+ix] - newpc[(size_t)(bbv*3+0)*MM+mmv];
        sdy[tid] = pc[(size_t)(bbv*3+1)*NN+ix] - newpc[(size_t)(bbv*3+1)*MM+mmv];
        sdz[tid] = pc[(size_t)(bbv*3+2)*NN+ix] - newpc[(size_t)(bbv*3+2)*MM+mmv];
    } else {
        if (tid < CPAD) { ssA[tid] = bns[tid]; stA[tid] = bnt[tid]; }
    }
    for (int e = tid; e < COUTB*CPAD/2; e += 256) {
        int o = e / (CPAD/2), cp = e - o*(CPAD/2);
        *(uint32_t*)(smem + WOFF + o*WSTR + cp*4) = ((const uint32_t*)Wh_b)[e];
    }
    __syncthreads();

    float4 xr[4];
    auto stage_load = [&](int kc) {
#pragma unroll
        for (int i = 0; i < 4; i++) {
            int e = tid + i*256, pos = e >> 2, c4 = e & 3;
            if (GATHER) {
                if (kc < 4) xr[i] = *(const float4*)&ft[sfb[pos] + kc*16 + c4*4];
                else xr[i] = (c4 == 0) ? make_float4(sdx[pos], sdy[pos], sdz[pos], 0.f)
                                       : make_float4(0.f, 0.f, 0.f, 0.f);
            } else {
                xr[i] = *(const float4*)&xin[(size_t)(pblock+pos)*CPAD + kc*16 + c4*4];
            }
        }
    };
    auto stage_conv = [&](int kc, int buf) {
        unsigned char* xh = smem + (buf*2+0)*XPLANE;
        unsigned char* xl = smem + (buf*2+1)*XPLANE;
#pragma unroll
        for (int i = 0; i < 4; i++) {
            int e = tid + i*256, pos = e >> 2, c4 = e & 3;
            float4 v = xr[i];
            if (!GATHER) {
                int c0 = kc*16 + c4*4;
                float4 sc = *(float4*)&ssA[c0];
                float4 tc = *(float4*)&stA[c0];
                v.x = fmaxf(v.x*sc.x+tc.x, 0.f); v.y = fmaxf(v.y*sc.y+tc.y, 0.f);
                v.z = fmaxf(v.z*sc.z+tc.z, 0.f); v.w = fmaxf(v.w*sc.w+tc.w, 0.f);
            }
            __half2 h01 = __floats2half2_rn(v.x, v.y);
            __half2 h23 = __floats2half2_rn(v.z, v.w);
            float2 r01 = __half22float2(h01);
            float2 r23 = __half22float2(h23);
            __half2 l01 = __floats2half2_rn(v.x - r01.x, v.y - r01.y);
            __half2 l23 = __floats2half2_rn(v.z - r23.x, v.w - r23.y);
            uint32_t off = pos*XROW + c4*8;
            *(uint2*)(xh + off) = make_uint2(*(uint32_t*)&h01, *(uint32_t*)&h23);
            *(uint2*)(xl + off) = make_uint2(*(uint32_t*)&l01, *(uint32_t*)&l23);
        }
    };

    const uint32_t base = smem_u32(smem);
    const uint32_t aoff = base + (uint32_t)((w*32 + (lane & 15))*XROW + (lane >> 4)*16);
    const uint32_t boff = base + WOFF +
        (uint32_t)((((lane >> 4) & 1)*8 + (lane & 7))*WSTR + ((lane >> 3) & 1)*16);

    float acc[2][COUTB/8][4];
#pragma unroll
    for (int t = 0; t < 2; t++)
#pragma unroll
        for (int n = 0; n < COUTB/8; n++)
#pragma unroll
            for (int c = 0; c < 4; c++) acc[t][n][c] = 0.f;

    stage_load(0); stage_conv(0, 0);
    __syncthreads();

    for (int kc = 0; kc < NK; kc++) {
        int buf = kc & 1;
        if (kc + 1 < NK) stage_load(kc + 1);
        uint32_t ah[2][4], al[2][4], bw[COUTB/16][4];
#pragma unroll
        for (int t = 0; t < 2; t++) {
            LDSMX4(ah[t], aoff + t*16*XROW + (buf*2+0)*XPLANE);
            LDSMX4(al[t], aoff + t*16*XROW + (buf*2+1)*XPLANE);
        }
#pragma unroll
        for (int j = 0; j < COUTB/16; j++)
            LDSMX4(bw[j], boff + j*16*WSTR + kc*32);
        // pass 1: all hi-term MMAs (independent accumulators)
#pragma unroll
        for (int j = 0; j < COUTB/16; j++)
#pragma unroll
            for (int t = 0; t < 2; t++) {
                MMAH(acc[t][2*j],   ah[t], bw[j][0], bw[j][1]);
                MMAH(acc[t][2*j+1], ah[t], bw[j][2], bw[j][3]);
            }
        // pass 2: lo-term MMAs (each depends on its pass-1 MMA at long distance)
#pragma unroll
        for (int j = 0; j < COUTB/16; j++)
#pragma unroll
            for (int t = 0; t < 2; t++) {
                MMAH(acc[t][2*j],   al[t], bw[j][0], bw[j][1]);
                MMAH(acc[t][2*j+1], al[t], bw[j][2], bw[j][3]);
            }
        if (kc + 1 < NK) stage_conv(kc + 1, buf ^ 1);
        __syncthreads();
    }

    const int q = lane >> 2, r2i = (lane & 3)*2;
#pragma unroll
    for (int nt = 0; nt < COUTB/8; nt++) {
        int ocl = nt*8 + r2i;
        int oc  = ocbase + ocl;
        float2 bv = *(const float2*)&bias[oc];
        float s1x = 0.f, s1y = 0.f, s2x = 0.f, s2y = 0.f;
        float mxx = -1e30f, mxy = -1e30f, mnx = 1e30f, mny = 1e30f;
#pragma unroll
        for (int t = 0; t < 2; t++) {
            float2 c01 = make_float2(acc[t][nt][0]+bv.x, acc[t][nt][1]+bv.y);
            float2 c23 = make_float2(acc[t][nt][2]+bv.x, acc[t][nt][3]+bv.y);
            if (!POOL) {
                *(float2*)&y[(size_t)(pblock + w*32 + t*16 + q)*cstride + oc]     = c01;
                *(float2*)&y[(size_t)(pblock + w*32 + t*16 + q + 8)*cstride + oc] = c23;
            }
            s1x += c01.x + c23.x;  s1y += c01.y + c23.y;
            s2x += c01.x*c01.x + c23.x*c23.x;
            s2y += c01.y*c01.y + c23.y*c23.y;
            mxx = fmaxf(mxx, fmaxf(c01.x, c23.x)); mxy = fmaxf(mxy, fmaxf(c01.y, c23.y));
            mnx = fminf(mnx, fminf(c01.x, c23.x)); mny = fminf(mny, fminf(c01.y, c23.y));
        }
#pragma unroll
        for (int o2 = 4; o2 <= 16; o2 <<= 1) {
            s1x += __shfl_xor_sync(0xffffffffu, s1x, o2);
            s1y += __shfl_xor_sync(0xffffffffu, s1y, o2);
            s2x += __shfl_xor_sync(0xffffffffu, s2x, o2);
            s2y += __shfl_xor_sync(0xffffffffu, s2y, o2);
            if (POOL) {
                mxx = fmaxf(mxx, __shfl_xor_sync(0xffffffffu, mxx, o2));
                mxy = fmaxf(mxy, __shfl_xor_sync(0xffffffffu, mxy, o2));
                mnx = fminf(mnx, __shfl_xor_sync(0xffffffffu, mnx, o2));
                mny = fminf(mny, __shfl_xor_sync(0xffffffffu, mny, o2));
            }
        }
        if (q == 0) {
            sm1[w*COUTB + ocl] = s1x; sm1[w*COUTB + ocl + 1] = s1y;
            sm2[w*COUTB + ocl] = s2x; sm2[w*COUTB + ocl + 1] = s2y;
            if (POOL) {
                if (KP == 32) {
                    size_t g = (size_t)(pblock >> 5) + w;
                    pmax[(size_t)oc*GCOUNT + g] = mxx; pmax[(size_t)(oc+1)*GCOUNT + g] = mxy;
                    pmin[(size_t)oc*GCOUNT + g] = mnx; pmin[(size_t)(oc+1)*GCOUNT + g] = mny;
                } else {
                    pmx[w*COUTB + ocl] = mxx; pmx[w*COUTB + ocl + 1] = mxy;
                    pmn[w*COUTB + ocl] = mnx; pmn[w*COUTB + ocl + 1] = mny;
                }
            }
        }
    }
    __syncthreads();
    for (int e = tid; e < COUTB; e += 256) {
        float a = 0.f, b2 = 0.f;
#pragma unroll
        for (int wi = 0; wi < 8; wi++) { a += sm1[wi*COUTB + e]; b2 += sm2[wi*COUTB + e]; }
        ps [(size_t)(ocbase + e)*nblk + blockIdx.x] = a;
        ps2[(size_t)(ocbase + e)*nblk + blockIdx.x] = b2;
    }
    if (POOL && KP == 64) {
        for (int e = tid; e < COUTB*4; e += 256) {
            int g = e / COUTB, ocl = e - g*COUTB;
            float mx = fmaxf(pmx[(g*2)*COUTB + ocl], pmx[(g*2+1)*COUTB + ocl]);
            float mn = fminf(pmn[(g*2)*COUTB + ocl], pmn[(g*2+1)*COUTB + ocl]);
            size_t gg = (size_t)(pblock >> 6) + g;
            pmax[(size_t)(ocbase + ocl)*GCOUNT + gg] = mx;
            pmin[(size_t)(ocbase + ocl)*GCOUNT + gg] = mn;
        }
    }
}

// ---------------- finalize BN ----------------
__global__ __launch_bounds__(256) void finalize_kernel(const float* __restrict__ ps,
    const float* __restrict__ ps2, int nblk, float invP,
    const float* __restrict__ gamma, const float* __restrict__ beta,
    float* __restrict__ s, float* __restrict__ t)
{
    int c = blockIdx.x;
    float a = 0.f, b = 0.f;
    for (int i = threadIdx.x; i < nblk; i += 256) {
        a += ps [(size_t)c*nblk + i];
        b += ps2[(size_t)c*nblk + i];
    }
#pragma unroll
    for (int off = 16; off > 0; off >>= 1) {
        a += __shfl_down_sync(0xffffffffu, a, off);
        b += __shfl_down_sync(0xffffffffu, b, off);
    }
    __shared__ float sa[8], sb[8];
    int lane = threadIdx.x & 31, w = threadIdx.x >> 5;
    if (lane == 0) { sa[w] = a; sb[w] = b; }
    __syncthreads();
    if (threadIdx.x < 8) {
        a = sa[threadIdx.x]; b = sb[threadIdx.x];
#pragma unroll
        for (int off = 4; off > 0; off >>= 1) {
            a += __shfl_down_sync(0xffu, a, off);
            b += __shfl_down_sync(0xffu, b, off);
        }
        if (threadIdx.x == 0) {
            float mu = a * invP;
            float var = b * invP - mu*mu;
            float sc = gamma[c] / sqrtf(var + 1e-5f);
            s[c] = sc;
            t[c] = beta[c] - mu * sc;
        }
    }
}

// ---------------- pool apply ----------------
__global__ __launch_bounds__(256) void pool_apply_kernel(const float* __restrict__ pmax,
    const float* __restrict__ pmin, const float* __restrict__ s, const float* __restrict__ t,
    float* __restrict__ out, int chbase)
{
    int gid = blockIdx.x*256 + threadIdx.x;
    int oc = gid >> 14, g = gid & 16383;
    float sc = s[oc], tc = t[oc];
    float v = (sc > 0.f) ? pmax[gid] : pmin[gid];
    float r = fmaxf(v*sc + tc, 0.f);
    out[OUT_OFS + ((size_t)((g >> 10)*256 + chbase + oc))*MM + (g & 1023)] = r;
}

// ---------------- host ----------------
extern "C" void kernel_launch(void* const* d_in, const int* in_sizes, int n_in,
                              void* d_out, int out_size)
{
    const float* pc   = (const float*)d_in[0];
    const float* feat = (const float*)d_in[1];
    const float *bp[6], *gp[6], *bep[6];
    WPtrs wargs;
    for (int i = 0; i < 6; i++) {
        wargs.w[i] = (const float*)d_in[2 + 4*i];
        bp[i]  = (const float*)d_in[3 + 4*i];
        gp[i]  = (const float*)d_in[4 + 4*i];
        bep[i] = (const float*)d_in[5 + 4*i];
    }
    float* out = (float*)d_out;

    int *samp, *idx0, *idx1;
    float *bufA, *bufB, *ft, *sv, *tv, *ps, *ps2, *pmax, *pmin;
    uint16_t *wth;
    cudaGetSymbolAddress((void**)&samp, g_samp);
    cudaGetSymbolAddress((void**)&idx0, g_idx0);
    cudaGetSymbolAddress((void**)&idx1, g_idx1);
    cudaGetSymbolAddress((void**)&bufA, g_bufA);
    cudaGetSymbolAddress((void**)&bufB, g_bufB);
    cudaGetSymbolAddress((void**)&ft,   g_ft);
    cudaGetSymbolAddress((void**)&sv,   g_s);
    cudaGetSymbolAddress((void**)&tv,   g_t);
    cudaGetSymbolAddress((void**)&ps,   g_ps);
    cudaGetSymbolAddress((void**)&ps2,  g_ps2);
    cudaGetSymbolAddress((void**)&pmax, g_pmax);
    cudaGetSymbolAddress((void**)&pmin, g_pmin);
    cudaGetSymbolAddress((void**)&wth,  g_wth);

    // smem: 49152 (X hi/lo double-buffered) + COUTB*WSTR (W) + 5120 + 32*COUTB*4
    const int sm_A = 49152 + 64*176 + 5120 + 8192;   // gather 64x80 = 73728
    const int sm_B = 49152 + 64*144 + 5120 + 8192;   // 64x64        = 71680
    const int sm_D = 49152 + 48*144 + 5120 + 6144;   // 48x64        = 67328
    const int sm_E = 49152 + 64*208 + 5120 + 8192;   // 64x96 pool   = 75776
    cudaFuncSetAttribute(conv_mma<true,false,64,80,32>,  cudaFuncAttributeMaxDynamicSharedMemorySize, sm_A);
    cudaFuncSetAttribute(conv_mma<false,false,64,64,32>, cudaFuncAttributeMaxDynamicSharedMemorySize, sm_B);
    cudaFuncSetAttribute(conv_mma<false,true,64,64,32>,  cudaFuncAttributeMaxDynamicSharedMemorySize, sm_B);
    cudaFuncSetAttribute(conv_mma<false,false,48,64,32>, cudaFuncAttributeMaxDynamicSharedMemorySize, sm_D);
    cudaFuncSetAttribute(conv_mma<false,true,64,96,64>,  cudaFuncAttributeMaxDynamicSharedMemorySize, sm_E);

    wtr_kernel<<<6, 256>>>(wargs, wth);
    ftr_kernel<<<dim3(128, 2, BB), dim3(32, 8)>>>(feat, ft);
    fps_kernel<<<BB, 512>>>(pc, samp, out);
    ballquery2_kernel<<<dim3(BB,32), 256, 3*NN*sizeof(float)>>>(pc, samp, idx0, idx1, 0.01f, 0.04f);

    const int nb0 = P0/256, nb1 = P1/256;

    // branch 0: 67->64->64->128, K=32
    conv_mma<true,false,64,80,32><<<dim3(nb0,1), 256, sm_A>>>(nullptr, wth+0*12288,
        bp[0], nullptr, nullptr, bufA, ps, ps2, nullptr, nullptr, 64, pc, ft, out, idx0, 15, 5);
    finalize_kernel<<<64, 256>>>(ps, ps2, nb0, 1.f/P0, gp[0], bep[0], sv, tv);
    conv_mma<false,false,64,64,32><<<dim3(nb0,1), 256, sm_B>>>(bufA, wth+1*12288,
        bp[1], sv, tv, bufB, ps, ps2, nullptr, nullptr, 64, nullptr, nullptr, nullptr, nullptr, 0, 0);
    finalize_kernel<<<64, 256>>>(ps, ps2, nb0, 1.f/P0, gp[1], bep[1], sv, tv);
    conv_mma<false,true,64,64,32><<<dim3(nb0,2), 256, sm_B>>>(bufB, wth+2*12288,
        bp[2], sv, tv, nullptr, ps, ps2, pmax, pmin, 128, nullptr, nullptr, nullptr, nullptr, 0, 0);
    finalize_kernel<<<128, 256>>>(ps, ps2, nb0, 1.f/P0, gp[2], bep[2], sv, tv);
    pool_apply_kernel<<<(128*GCOUNT)/256, 256>>>(pmax, pmin, sv, tv, out, 0);

    // branch 1: 67->64->96->128, K=64
    conv_mma<true,false,64,80,32><<<dim3(nb1,1), 256, sm_A>>>(nullptr, wth+3*12288,
        bp[3], nullptr, nullptr, bufA, ps, ps2, nullptr, nullptr, 64, pc, ft, out, idx1, 16, 6);
    finalize_kernel<<<64, 256>>>(ps, ps2, nb1, 1.f/P1, gp[3], bep[3], sv, tv);
    conv_mma<false,false,48,64,32><<<dim3(nb1,2), 256, sm_D>>>(bufA, wth+4*12288,
        bp[4], sv, tv, bufB, ps, ps2, nullptr, nullptr, 96, nullptr, nullptr, nullptr, nullptr, 0, 0);
    finalize_kernel<<<96, 256>>>(ps, ps2, nb1, 1.f/P1, gp[4], bep[4], sv, tv);
    conv_mma<false,true,64,96,64><<<dim3(nb1,2), 256, sm_E>>>(bufB, wth+5*12288,
        bp[5], sv, tv, nullptr, ps, ps2, pmax, pmin, 128, nullptr, nullptr, nullptr, nullptr, 0, 0);
    finalize_kernel<<<128, 256>>>(ps, ps2, nb1, 1.f/P1, gp[5], bep[5], sv, tv);
    pool_apply_kernel<<<(128*GCOUNT)/256, 256>>>(pmax, pmin, sv, tv, out, 128);
}

// round 12
// speedup vs baseline: 1.3836x; 1.0509x over previous
#include <cuda_runtime.h>
#include <cuda_fp16.h>
#include <cstdint>

#define BB 16
#define NN 4096
#define MM 1024
#define P0 (BB*MM*32)
#define P1 (BB*MM*64)
#define OUT_OFS (BB*3*MM)
#define GCOUNT (BB*MM)

__device__ int      g_samp[BB*MM];
__device__ int      g_idx0[P0];
__device__ int      g_idx1[P1];
__device__ float    g_bufA[64*P1];
__device__ float    g_bufB[96*P1];
__device__ __half   g_fth[BB*NN*64];   // fp16 transposed features (B,N,64)
__device__ float    g_s[128];
__device__ float    g_t[128];
__device__ float    g_ps [128*8192];
__device__ float    g_ps2[128*8192];
__device__ float    g_pmax[128*GCOUNT];
__device__ float    g_pmin[128*GCOUNT];
__device__ uint16_t g_wth[6*12288];    // fp16 hi weights [l][out][cpad]
__device__ uint16_t g_wtl[6*12288];    // fp16 lo weights

struct WPtrs { const float* w[6]; };

__device__ __forceinline__ uint32_t smem_u32(const void* p) {
    uint32_t a;
    asm("{ .reg .u64 t; cvta.to.shared.u64 t, %1; cvt.u32.u64 %0, t; }" : "=r"(a) : "l"(p));
    return a;
}
#define LDSMX4(r, addr) \
    asm volatile("ldmatrix.sync.aligned.m8n8.x4.shared.b16 {%0,%1,%2,%3}, [%4];" \
        : "=r"((r)[0]), "=r"((r)[1]), "=r"((r)[2]), "=r"((r)[3]) : "r"(addr))
#define MMAH(c, a, b0v, b1v) \
    asm volatile("mma.sync.aligned.m16n8k16.row.col.f32.f16.f16.f32 " \
        "{%0,%1,%2,%3}, {%4,%5,%6,%7}, {%8,%9}, {%0,%1,%2,%3};" \
        : "+f"((c)[0]), "+f"((c)[1]), "+f"((c)[2]), "+f"((c)[3]) \
        : "r"((a)[0]), "r"((a)[1]), "r"((a)[2]), "r"((a)[3]), "r"(b0v), "r"(b1v))

// ---------------- weights: permute + fp16 hi/lo split, [l][out][cpad] ----------------
__global__ void wtr_kernel(WPtrs wp, uint16_t* __restrict__ wth, uint16_t* __restrict__ wtl)
{
    const int cins[6]  = {67, 64, 64, 67, 64, 96};
    const int cpads[6] = {80, 64, 64, 80, 64, 96};
    const int couts[6] = {64, 64, 128, 64, 96, 128};
    const int gat[6]   = {1, 0, 0, 1, 0, 0};
    int l = blockIdx.x;
    const float* W = wp.w[l];
    int cin = cins[l], cpad = cpads[l], cout = couts[l];
    for (int e = threadIdx.x; e < cout*cpad; e += 256) {
        int o = e / cpad, c = e - o*cpad;
        int src;
        if (gat[l]) src = (c < 64) ? c + 3 : (c < 67 ? c - 64 : -1);
        else        src = (c < cin) ? c : -1;
        float wf = (src >= 0) ? W[o*cin + src] : 0.0f;
        __half h = __float2half_rn(wf);
        __half lo = __float2half_rn(wf - __half2float(h));
        wth[l*12288 + e] = *reinterpret_cast<uint16_t*>(&h);
        wtl[l*12288 + e] = *reinterpret_cast<uint16_t*>(&lo);
    }
}

// ---------------- feature transpose -> fp16 (B,N,64) ----------------
__global__ __launch_bounds__(256) void ftr_kernel(const float* __restrict__ feat,
                                                  __half* __restrict__ fth)
{
    __shared__ float tile[32][33];
    int b = blockIdx.z, c0 = blockIdx.y*32, n0 = blockIdx.x*32;
    int tx = threadIdx.x, ty = threadIdx.y;
#pragma unroll
    for (int k = 0; k < 4; k++)
        tile[ty + k*8][tx] = feat[(size_t)(b*64 + c0 + ty + k*8)*NN + n0 + tx];
    __syncthreads();
#pragma unroll
    for (int k = 0; k < 4; k++)
        fth[((size_t)b*NN + n0 + ty + k*8)*64 + c0 + tx] = __float2half_rn(tile[tx][ty + k*8]);
}

// ---------------- FPS ----------------
__global__ __launch_bounds__(512) void fps_kernel(const float* __restrict__ pc,
                                                  int* __restrict__ samp,
                                                  float* __restrict__ dout)
{
    int b = blockIdx.x, tid = threadIdx.x;
    const float* px = pc + (size_t)b*3*NN;
    const float* py = px + NN;
    const float* pz = py + NN;
    float x[8], yv[8], z[8], dmin[8];
#pragma unroll
    for (int j = 0; j < 8; j++) {
        int i = tid + j*512;
        x[j] = px[i]; yv[j] = py[i]; z[j] = pz[i]; dmin[j] = 1e10f;
    }
    __shared__ unsigned svu[2][16], siu[2][16];
    int lane = tid & 31, w = tid >> 5, far = 0;
    for (int it = 0; it < MM; it++) {
        int buf = it & 1;
        if (tid == 0) {
            samp[b*MM + it] = far;
            dout[(b*3+0)*MM + it] = px[far];
            dout[(b*3+1)*MM + it] = py[far];
            dout[(b*3+2)*MM + it] = pz[far];
        }
        float cx = px[far], cy = py[far], cz = pz[far];
        float bv = -1.0f; int bi = 0;
#pragma unroll
        for (int j = 0; j < 8; j++) {
            float dx = x[j]-cx, dy = yv[j]-cy, dz = z[j]-cz;
            float d = __fadd_rn(__fadd_rn(__fmul_rn(dx,dx), __fmul_rn(dy,dy)), __fmul_rn(dz,dz));
            float nd = fminf(dmin[j], d);
            dmin[j] = nd;
            if (nd > bv) { bv = nd; bi = tid + j*512; }
        }
        unsigned fb = __float_as_uint(bv);
        unsigned mw = __reduce_max_sync(0xffffffffu, fb);
        unsigned mi = __reduce_min_sync(0xffffffffu, (fb == mw) ? (unsigned)bi : 0xffffffffu);
        if (lane == 0) { svu[buf][w] = mw; siu[buf][w] = mi; }
        __syncthreads();
        unsigned f2 = (lane < 16) ? svu[buf][lane] : 0u;
        unsigned i2 = (lane < 16) ? siu[buf][lane] : 0xffffffffu;
        unsigned m2 = __reduce_max_sync(0xffffffffu, f2);
        far = (int)__reduce_min_sync(0xffffffffu, (f2 == m2) ? i2 : 0xffffffffu);
    }
}

// ---------------- dual-radius ball query ----------------
__global__ __launch_bounds__(256) void ballquery2_kernel(const float* __restrict__ pc,
    const int* __restrict__ samp, int* __restrict__ gidx0, int* __restrict__ gidx1,
    float r2a, float r2b)
{
    extern __shared__ float sh[];
    float* sx = sh; float* sy = sh + NN; float* sz = sh + 2*NN;
    int b = blockIdx.x;
    const float* px = pc + (size_t)b*3*NN;
    for (int i = threadIdx.x; i < NN; i += blockDim.x) {
        sx[i] = px[i]; sy[i] = px[NN+i]; sz[i] = px[2*NN+i];
    }
    __syncthreads();
    int lane = threadIdx.x & 31, wid = threadIdx.x >> 5;
    int mstart = blockIdx.y * 32;
    unsigned lt = (1u << lane) - 1u;
    for (int m = mstart + wid; m < mstart + 32; m += 8) {
        int ci = samp[b*MM + m];
        float cx = sx[ci], cy = sy[ci], cz = sz[ci];
        int cnt0 = 0, cnt1 = 0, f0 = -1, f1 = -1;
        int* out0 = gidx0 + ((size_t)(b*MM + m))*32;
        int* out1 = gidx1 + ((size_t)(b*MM + m))*64;
        for (int base = 0; base < NN && (cnt0 < 32 || cnt1 < 64); base += 32) {
            int i = base + lane;
            float dx = sx[i]-cx, dy = sy[i]-cy, dz = sz[i]-cz;
            float d = __fadd_rn(__fadd_rn(__fmul_rn(dx,dx), __fmul_rn(dy,dy)), __fmul_rn(dz,dz));
            bool ok0 = d < r2a, ok1 = d < r2b;
            unsigned m0 = __ballot_sync(0xffffffffu, ok0);
            unsigned m1 = __ballot_sync(0xffffffffu, ok1);
            if (f0 < 0 && m0) f0 = base + __ffs(m0) - 1;
            if (f1 < 0 && m1) f1 = base + __ffs(m1) - 1;
            int p0 = cnt0 + __popc(m0 & lt);
            int p1 = cnt1 + __popc(m1 & lt);
            if (ok0 && p0 < 32) out0[p0] = i;
            if (ok1 && p1 < 64) out1[p1] = i;
            cnt0 = min(32, cnt0 + __popc(m0));
            cnt1 = min(64, cnt1 + __popc(m1));
        }
        for (int p = cnt0 + lane; p < 32; p += 32) out0[p] = f0;
        for (int p = cnt1 + lane; p < 64; p += 32) out1[p] = f1;
    }
}

// ---------------- tensor-core conv: X single fp16 term, W fp16 hi/lo ----------------
template<bool GATHER, bool POOL, int COUTB, int CPAD, int KP>
__global__ __launch_bounds__(256, 2) void conv_mma(
    const float* __restrict__ xin,
    const uint16_t* __restrict__ Whi, const uint16_t* __restrict__ Wlo,
    const float* __restrict__ bias,
    const float* __restrict__ bns, const float* __restrict__ bnt,
    float* __restrict__ y, float* __restrict__ ps, float* __restrict__ ps2,
    float* __restrict__ pmax, float* __restrict__ pmin,
    int cstride,
    const float* __restrict__ pc, const __half* __restrict__ fth,
    const float* __restrict__ newpc, const int* __restrict__ gidx,
    int mkshift, int kshift)
{
    constexpr int NK = CPAD/16;
    constexpr int WSTR = CPAD*2 + 16;
    constexpr int XROW = 48, XPLANE = 256*XROW;
    constexpr int WOFF = 2*XPLANE;                 // 24576
    constexpr int MOFF = WOFF + 2*COUTB*WSTR;

    extern __shared__ __align__(16) unsigned char smem[];
    float* ssA = (float*)(smem + MOFF);
    float* stA = (float*)(smem + MOFF + 512);
    unsigned* sfb = (unsigned*)(smem + MOFF + 1024);
    float* sdx = (float*)(smem + MOFF + 2048);
    float* sdy = (float*)(smem + MOFF + 3072);
    float* sdz = (float*)(smem + MOFF + 4096);
    float* sm1 = (float*)(smem + MOFF + 5120);
    float* sm2 = sm1 + 8*COUTB;
    float* pmx = sm2 + 8*COUTB;
    float* pmn = pmx + 8*COUTB;

    const int tid = threadIdx.x, lane = tid & 31, w = tid >> 5;
    const int pblock = blockIdx.x * 256;
    const int ocbase = blockIdx.y * COUTB;
    const int nblk = gridDim.x;
    const uint16_t* Whi_b = Whi + (size_t)ocbase*CPAD;
    const uint16_t* Wlo_b = Wlo + (size_t)ocbase*CPAD;

    if (GATHER) {
        int p = pblock + tid;
        int bbv = p >> mkshift, mmv = (p >> kshift) & (MM-1);
        int ix = gidx[p];
        sfb[tid] = (unsigned)((bbv*NN + ix) * 64);
        sdx[tid] = pc[(size_t)(bbv*3+0)*NN+ix] - newpc[(size_t)(bbv*3+0)*MM+mmv];
        sdy[tid] = pc[(size_t)(bbv*3+1)*NN+ix] - newpc[(size_t)(bbv*3+1)*MM+mmv];
        sdz[tid] = pc[(size_t)(bbv*3+2)*NN+ix] - newpc[(size_t)(bbv*3+2)*MM+mmv];
    } else {
        if (tid < CPAD) { ssA[tid] = bns[tid]; stA[tid] = bnt[tid]; }
    }
    for (int e = tid; e < COUTB*CPAD/2; e += 256) {
        int o = e / (CPAD/2), cp = e - o*(CPAD/2);
        *(uint32_t*)(smem + WOFF + o*WSTR + cp*4) = ((const uint32_t*)Whi_b)[e];
        *(uint32_t*)(smem + WOFF + COUTB*WSTR + o*WSTR + cp*4) = ((const uint32_t*)Wlo_b)[e];
    }
    __syncthreads();

    float4 xr[4];
    uint2  hr[4];
    auto stage_load = [&](int kc) {
#pragma unroll
        for (int i = 0; i < 4; i++) {
            int e = tid + i*256, pos = e >> 2, c4 = e & 3;
            if (GATHER) {
                if (kc < 4) hr[i] = *(const uint2*)&fth[sfb[pos] + kc*16 + c4*4];
            } else {
                xr[i] = *(const float4*)&xin[(size_t)(pblock+pos)*CPAD + kc*16 + c4*4];
            }
        }
    };
    auto stage_conv = [&](int kc, int buf) {
        unsigned char* xh = smem + buf*XPLANE;
#pragma unroll
        for (int i = 0; i < 4; i++) {
            int e = tid + i*256, pos = e >> 2, c4 = e & 3;
            uint2 o2v;
            if (GATHER) {
                if (kc < 4) o2v = hr[i];
                else if (c4 == 0) {
                    __half2 a = __floats2half2_rn(sdx[pos], sdy[pos]);
                    __half2 b = __floats2half2_rn(sdz[pos], 0.f);
                    o2v = make_uint2(*(uint32_t*)&a, *(uint32_t*)&b);
                } else o2v = make_uint2(0u, 0u);
            } else {
                int c0 = kc*16 + c4*4;
                float4 v = xr[i];
                float4 sc = *(float4*)&ssA[c0];
                float4 tc = *(float4*)&stA[c0];
                v.x = fmaxf(v.x*sc.x+tc.x, 0.f); v.y = fmaxf(v.y*sc.y+tc.y, 0.f);
                v.z = fmaxf(v.z*sc.z+tc.z, 0.f); v.w = fmaxf(v.w*sc.w+tc.w, 0.f);
                __half2 a = __floats2half2_rn(v.x, v.y);
                __half2 b = __floats2half2_rn(v.z, v.w);
                o2v = make_uint2(*(uint32_t*)&a, *(uint32_t*)&b);
            }
            *(uint2*)(xh + pos*XROW + c4*8) = o2v;
        }
    };

    const uint32_t base = smem_u32(smem);
    const uint32_t aoff = base + (uint32_t)((w*32 + (lane & 15))*XROW + (lane >> 4)*16);
    const uint32_t boff = base + WOFF +
        (uint32_t)((((lane >> 4) & 1)*8 + (lane & 7))*WSTR + ((lane >> 3) & 1)*16);

    float acc[2][COUTB/8][4];
#pragma unroll
    for (int t = 0; t < 2; t++)
#pragma unroll
        for (int n = 0; n < COUTB/8; n++)
#pragma unroll
            for (int c = 0; c < 4; c++) acc[t][n][c] = 0.f;

    stage_load(0); stage_conv(0, 0);
    __syncthreads();

    for (int kc = 0; kc < NK; kc++) {
        int buf = kc & 1;
        if (kc + 1 < NK) stage_load(kc + 1);
        uint32_t ah[2][4], bh[COUTB/16][4], bl[COUTB/16][4];
#pragma unroll
        for (int t = 0; t < 2; t++)
            LDSMX4(ah[t], aoff + t*16*XROW + buf*XPLANE);
#pragma unroll
        for (int j = 0; j < COUTB/16; j++) {
            LDSMX4(bh[j], boff + j*16*WSTR + kc*32);
            LDSMX4(bl[j], boff + COUTB*WSTR + j*16*WSTR + kc*32);
        }
        // pass 1: hi-W MMAs (independent accs)
#pragma unroll
        for (int j = 0; j < COUTB/16; j++)
#pragma unroll
            for (int t = 0; t < 2; t++) {
                MMAH(acc[t][2*j],   ah[t], bh[j][0], bh[j][1]);
                MMAH(acc[t][2*j+1], ah[t], bh[j][2], bh[j][3]);
            }
        // pass 2: lo-W MMAs
#pragma unroll
        for (int j = 0; j < COUTB/16; j++)
#pragma unroll
            for (int t = 0; t < 2; t++) {
                MMAH(acc[t][2*j],   ah[t], bl[j][0], bl[j][1]);
                MMAH(acc[t][2*j+1], ah[t], bl[j][2], bl[j][3]);
            }
        if (kc + 1 < NK) stage_conv(kc + 1, buf ^ 1);
        __syncthreads();
    }

    const int q = lane >> 2, r2i = (lane & 3)*2;
#pragma unroll
    for (int nt = 0; nt < COUTB/8; nt++) {
        int ocl = nt*8 + r2i;
        int oc  = ocbase + ocl;
        float2 bv = *(const float2*)&bias[oc];
        float s1x = 0.f, s1y = 0.f, s2x = 0.f, s2y = 0.f;
        float mxx = -1e30f, mxy = -1e30f, mnx = 1e30f, mny = 1e30f;
#pragma unroll
        for (int t = 0; t < 2; t++) {
            float2 c01 = make_float2(acc[t][nt][0]+bv.x, acc[t][nt][1]+bv.y);
            float2 c23 = make_float2(acc[t][nt][2]+bv.x, acc[t][nt][3]+bv.y);
            if (!POOL) {
                *(float2*)&y[(size_t)(pblock + w*32 + t*16 + q)*cstride + oc]     = c01;
                *(float2*)&y[(size_t)(pblock + w*32 + t*16 + q + 8)*cstride + oc] = c23;
            }
            s1x += c01.x + c23.x;  s1y += c01.y + c23.y;
            s2x += c01.x*c01.x + c23.x*c23.x;
            s2y += c01.y*c01.y + c23.y*c23.y;
            mxx = fmaxf(mxx, fmaxf(c01.x, c23.x)); mxy = fmaxf(mxy, fmaxf(c01.y, c23.y));
            mnx = fminf(mnx, fminf(c01.x, c23.x)); mny = fminf(mny, fminf(c01.y, c23.y));
        }
#pragma unroll
        for (int o2 = 4; o2 <= 16; o2 <<= 1) {
            s1x += __shfl_xor_sync(0xffffffffu, s1x, o2);
            s1y += __shfl_xor_sync(0xffffffffu, s1y, o2);
            s2x += __shfl_xor_sync(0xffffffffu, s2x, o2);
            s2y += __shfl_xor_sync(0xffffffffu, s2y, o2);
            if (POOL) {
                mxx = fmaxf(mxx, __shfl_xor_sync(0xffffffffu, mxx, o2));
                mxy = fmaxf(mxy, __shfl_xor_sync(0xffffffffu, mxy, o2));
                mnx = fminf(mnx, __shfl_xor_sync(0xffffffffu, mnx, o2));
                mny = fminf(mny, __shfl_xor_sync(0xffffffffu, mny, o2));
            }
        }
        if (q == 0) {
            sm1[w*COUTB + ocl] = s1x; sm1[w*COUTB + ocl + 1] = s1y;
            sm2[w*COUTB + ocl] = s2x; sm2[w*COUTB + ocl + 1] = s2y;
            if (POOL) {
                if (KP == 32) {
                    size_t g = (size_t)(pblock >> 5) + w;
                    pmax[(size_t)oc*GCOUNT + g] = mxx; pmax[(size_t)(oc+1)*GCOUNT + g] = mxy;
                    pmin[(size_t)oc*GCOUNT + g] = mnx; pmin[(size_t)(oc+1)*GCOUNT + g] = mny;
                } else {
                    pmx[w*COUTB + ocl] = mxx; pmx[w*COUTB + ocl + 1] = mxy;
                    pmn[w*COUTB + ocl] = mnx; pmn[w*COUTB + ocl + 1] = mny;
                }
            }
        }
    }
    __syncthreads();
    for (int e = tid; e < COUTB; e += 256) {
        float a = 0.f, b2 = 0.f;
#pragma unroll
        for (int wi = 0; wi < 8; wi++) { a += sm1[wi*COUTB + e]; b2 += sm2[wi*COUTB + e]; }
        ps [(size_t)(ocbase + e)*nblk + blockIdx.x] = a;
        ps2[(size_t)(ocbase + e)*nblk + blockIdx.x] = b2;
    }
    if (POOL && KP == 64) {
        for (int e = tid; e < COUTB*4; e += 256) {
            int g = e / COUTB, ocl = e - g*COUTB;
            float mx = fmaxf(pmx[(g*2)*COUTB + ocl], pmx[(g*2+1)*COUTB + ocl]);
            float mn = fminf(pmn[(g*2)*COUTB + ocl], pmn[(g*2+1)*COUTB + ocl]);
            size_t gg = (size_t)(pblock >> 6) + g;
            pmax[(size_t)(ocbase + ocl)*GCOUNT + gg] = mx;
            pmin[(size_t)(ocbase + ocl)*GCOUNT + gg] = mn;
        }
    }
}

// ---------------- finalize BN ----------------
__global__ __launch_bounds__(256) void finalize_kernel(const float* __restrict__ ps,
    const float* __restrict__ ps2, int nblk, float invP,
    const float* __restrict__ gamma, const float* __restrict__ beta,
    float* __restrict__ s, float* __restrict__ t)
{
    int c = blockIdx.x;
    float a = 0.f, b = 0.f;
    for (int i = threadIdx.x; i < nblk; i += 256) {
        a += ps [(size_t)c*nblk + i];
        b += ps2[(size_t)c*nblk + i];
    }
#pragma unroll
    for (int off = 16; off > 0; off >>= 1) {
        a += __shfl_down_sync(0xffffffffu, a, off);
        b += __shfl_down_sync(0xffffffffu, b, off);
    }
    __shared__ float sa[8], sb[8];
    int lane = threadIdx.x & 31, w = threadIdx.x >> 5;
    if (lane == 0) { sa[w] = a; sb[w] = b; }
    __syncthreads();
    if (threadIdx.x < 8) {
        a = sa[threadIdx.x]; b = sb[threadIdx.x];
#pragma unroll
        for (int off = 4; off > 0; off >>= 1) {
            a += __shfl_down_sync(0xffu, a, off);
            b += __shfl_down_sync(0xffu, b, off);
        }
        if (threadIdx.x == 0) {
            float mu = a * invP;
            float var = b * invP - mu*mu;
            float sc = gamma[c] / sqrtf(var + 1e-5f);
            s[c] = sc;
            t[c] = beta[c] - mu * sc;
        }
    }
}

// ---------------- pool apply ----------------
__global__ __launch_bounds__(256) void pool_apply_kernel(const float* __restrict__ pmax,
    const float* __restrict__ pmin, const float* __restrict__ s, const float* __restrict__ t,
    float* __restrict__ out, int chbase)
{
    int gid = blockIdx.x*256 + threadIdx.x;
    int oc = gid >> 14, g = gid & 16383;
    float sc = s[oc], tc = t[oc];
    float v = (sc > 0.f) ? pmax[gid] : pmin[gid];
    float r = fmaxf(v*sc + tc, 0.f);
    out[OUT_OFS + ((size_t)((g >> 10)*256 + chbase + oc))*MM + (g & 1023)] = r;
}

// ---------------- host ----------------
extern "C" void kernel_launch(void* const* d_in, const int* in_sizes, int n_in,
                              void* d_out, int out_size)
{
    const float* pc   = (const float*)d_in[0];
    const float* feat = (const float*)d_in[1];
    const float *bp[6], *gp[6], *bep[6];
    WPtrs wargs;
    for (int i = 0; i < 6; i++) {
        wargs.w[i] = (const float*)d_in[2 + 4*i];
        bp[i]  = (const float*)d_in[3 + 4*i];
        gp[i]  = (const float*)d_in[4 + 4*i];
        bep[i] = (const float*)d_in[5 + 4*i];
    }
    float* out = (float*)d_out;

    int *samp, *idx0, *idx1;
    float *bufA, *bufB, *sv, *tv, *ps, *ps2, *pmax, *pmin;
    __half* fth;
    uint16_t *wth, *wtl;
    cudaGetSymbolAddress((void**)&samp, g_samp);
    cudaGetSymbolAddress((void**)&idx0, g_idx0);
    cudaGetSymbolAddress((void**)&idx1, g_idx1);
    cudaGetSymbolAddress((void**)&bufA, g_bufA);
    cudaGetSymbolAddress((void**)&bufB, g_bufB);
    cudaGetSymbolAddress((void**)&fth,  g_fth);
    cudaGetSymbolAddress((void**)&sv,   g_s);
    cudaGetSymbolAddress((void**)&tv,   g_t);
    cudaGetSymbolAddress((void**)&ps,   g_ps);
    cudaGetSymbolAddress((void**)&ps2,  g_ps2);
    cudaGetSymbolAddress((void**)&pmax, g_pmax);
    cudaGetSymbolAddress((void**)&pmin, g_pmin);
    cudaGetSymbolAddress((void**)&wth,  g_wth);
    cudaGetSymbolAddress((void**)&wtl,  g_wtl);

    // smem: 24576 (X fp16 double-buffered) + 2*COUTB*WSTR (W hi/lo) + 5120 + 32*COUTB*4
    const int sm_A = 24576 + 2*64*176 + 5120 + 8192;   // gather 64x80 = 60416
    const int sm_B = 24576 + 2*64*144 + 5120 + 8192;   // 64x64        = 56320
    const int sm_D = 24576 + 2*48*144 + 5120 + 6144;   // 48x64        = 49664
    const int sm_E = 24576 + 2*64*208 + 5120 + 8192;   // 64x96 pool   = 64512
    cudaFuncSetAttribute(conv_mma<true,false,64,80,32>,  cudaFuncAttributeMaxDynamicSharedMemorySize, sm_A);
    cudaFuncSetAttribute(conv_mma<false,false,64,64,32>, cudaFuncAttributeMaxDynamicSharedMemorySize, sm_B);
    cudaFuncSetAttribute(conv_mma<false,true,64,64,32>,  cudaFuncAttributeMaxDynamicSharedMemorySize, sm_B);
    cudaFuncSetAttribute(conv_mma<false,false,48,64,32>, cudaFuncAttributeMaxDynamicSharedMemorySize, sm_D);
    cudaFuncSetAttribute(conv_mma<false,true,64,96,64>,  cudaFuncAttributeMaxDynamicSharedMemorySize, sm_E);

    wtr_kernel<<<6, 256>>>(wargs, wth, wtl);
    ftr_kernel<<<dim3(128, 2, BB), dim3(32, 8)>>>(feat, fth);
    fps_kernel<<<BB, 512>>>(pc, samp, out);
    ballquery2_kernel<<<dim3(BB,32), 256, 3*NN*sizeof(float)>>>(pc, samp, idx0, idx1, 0.01f, 0.04f);

    const int nb0 = P0/256, nb1 = P1/256;

    // branch 0: 67->64->64->128, K=32
    conv_mma<true,false,64,80,32><<<dim3(nb0,1), 256, sm_A>>>(nullptr, wth+0*12288, wtl+0*12288,
        bp[0], nullptr, nullptr, bufA, ps, ps2, nullptr, nullptr, 64, pc, fth, out, idx0, 15, 5);
    finalize_kernel<<<64, 256>>>(ps, ps2, nb0, 1.f/P0, gp[0], bep[0], sv, tv);
    conv_mma<false,false,64,64,32><<<dim3(nb0,1), 256, sm_B>>>(bufA, wth+1*12288, wtl+1*12288,
        bp[1], sv, tv, bufB, ps, ps2, nullptr, nullptr, 64, nullptr, nullptr, nullptr, nullptr, 0, 0);
    finalize_kernel<<<64, 256>>>(ps, ps2, nb0, 1.f/P0, gp[1], bep[1], sv, tv);
    conv_mma<false,true,64,64,32><<<dim3(nb0,2), 256, sm_B>>>(bufB, wth+2*12288, wtl+2*12288,
        bp[2], sv, tv, nullptr, ps, ps2, pmax, pmin, 128, nullptr, nullptr, nullptr, nullptr, 0, 0);
    finalize_kernel<<<128, 256>>>(ps, ps2, nb0, 1.f/P0, gp[2], bep[2], sv, tv);
    pool_apply_kernel<<<(128*GCOUNT)/256, 256>>>(pmax, pmin, sv, tv, out, 0);

    // branch 1: 67->64->96->128, K=64
    conv_mma<true,false,64,80,32><<<dim3(nb1,1), 256, sm_A>>>(nullptr, wth+3*12288, wtl+3*12288,
        bp[3], nullptr, nullptr, bufA, ps, ps2, nullptr, nullptr, 64, pc, fth, out, idx1, 16, 6);
    finalize_kernel<<<64, 256>>>(ps, ps2, nb1, 1.f/P1, gp[3], bep[3], sv, tv);
    conv_mma<false,false,48,64,32><<<dim3(nb1,2), 256, sm_D>>>(bufA, wth+4*12288, wtl+4*12288,
        bp[4], sv, tv, bufB, ps, ps2, nullptr, nullptr, 96, nullptr, nullptr, nullptr, nullptr, 0, 0);
    finalize_kernel<<<96, 256>>>(ps, ps2, nb1, 1.f/P1, gp[4], bep[4], sv, tv);
    conv_mma<false,true,64,96,64><<<dim3(nb1,2), 256, sm_E>>>(bufB, wth+5*12288, wtl+5*12288,
        bp[5], sv, tv, nullptr, ps, ps2, pmax, pmin, 128, nullptr, nullptr, nullptr, nullptr, 0, 0);
    finalize_kernel<<<128, 256>>>(ps, ps2, nb1, 1.f/P1, gp[5], bep[5], sv, tv);
    pool_apply_kernel<<<(128*GCOUNT)/256, 256>>>(pmax, pmin, sv, tv, out, 128);
}

// round 13
// speedup vs baseline: 1.4762x; 1.0669x over previous
#include <cuda_runtime.h>
#include <cuda_fp16.h>
#include <cstdint>

#define BB 16
#define NN 4096
#define MM 1024
#define P0 (BB*MM*32)
#define P1 (BB*MM*64)
#define OUT_OFS (BB*3*MM)
#define GCOUNT (BB*MM)

__device__ int      g_samp[BB*MM];
__device__ int      g_idx0[P0];
__device__ int      g_idx1[P1];
__device__ __half   g_bufA[64*P1];     // fp16 layer-1 out [pos][c]
__device__ __half   g_bufB[96*P1];     // fp16 layer-2 out
__device__ __half   g_fth[BB*NN*64];   // fp16 transposed features (B,N,64)
__device__ float    g_s[128];
__device__ float    g_t[128];
__device__ float    g_ps [128*8192];
__device__ float    g_ps2[128*8192];
__device__ float    g_pmax[128*GCOUNT];
__device__ float    g_pmin[128*GCOUNT];
__device__ uint16_t g_wth[6*12288];
__device__ uint16_t g_wtl[6*12288];

struct WPtrs { const float* w[6]; };

__device__ __forceinline__ uint32_t smem_u32(const void* p) {
    uint32_t a;
    asm("{ .reg .u64 t; cvta.to.shared.u64 t, %1; cvt.u32.u64 %0, t; }" : "=r"(a) : "l"(p));
    return a;
}
#define LDSMX4(r, addr) \
    asm volatile("ldmatrix.sync.aligned.m8n8.x4.shared.b16 {%0,%1,%2,%3}, [%4];" \
        : "=r"((r)[0]), "=r"((r)[1]), "=r"((r)[2]), "=r"((r)[3]) : "r"(addr))
#define MMAH(c, a, b0v, b1v) \
    asm volatile("mma.sync.aligned.m16n8k16.row.col.f32.f16.f16.f32 " \
        "{%0,%1,%2,%3}, {%4,%5,%6,%7}, {%8,%9}, {%0,%1,%2,%3};" \
        : "+f"((c)[0]), "+f"((c)[1]), "+f"((c)[2]), "+f"((c)[3]) \
        : "r"((a)[0]), "r"((a)[1]), "r"((a)[2]), "r"((a)[3]), "r"(b0v), "r"(b1v))

// ---------------- feature transpose -> fp16 (B,N,64) ----------------
__global__ __launch_bounds__(256) void ftr_kernel(const float* __restrict__ feat,
                                                  __half* __restrict__ fth)
{
    __shared__ float tile[32][33];
    int b = blockIdx.z, c0 = blockIdx.y*32, n0 = blockIdx.x*32;
    int tx = threadIdx.x, ty = threadIdx.y;
#pragma unroll
    for (int k = 0; k < 4; k++)
        tile[ty + k*8][tx] = feat[(size_t)(b*64 + c0 + ty + k*8)*NN + n0 + tx];
    __syncthreads();
#pragma unroll
    for (int k = 0; k < 4; k++)
        fth[((size_t)b*NN + n0 + ty + k*8)*64 + c0 + tx] = __float2half_rn(tile[tx][ty + k*8]);
}

// ---------------- FPS (blocks 0..15) + weight split (blocks 16..21) ----------------
__global__ __launch_bounds__(512) void fps_kernel(const float* __restrict__ pc,
                                                  int* __restrict__ samp,
                                                  float* __restrict__ dout,
                                                  WPtrs wp,
                                                  uint16_t* __restrict__ wth,
                                                  uint16_t* __restrict__ wtl)
{
    if (blockIdx.x >= BB) {   // weight permute + fp16 hi/lo split
        const int cins[6]  = {67, 64, 64, 67, 64, 96};
        const int cpads[6] = {80, 64, 64, 80, 64, 96};
        const int couts[6] = {64, 64, 128, 64, 96, 128};
        const int gat[6]   = {1, 0, 0, 1, 0, 0};
        int l = blockIdx.x - BB;
        const float* W = wp.w[l];
        int cin = cins[l], cpad = cpads[l], cout = couts[l];
        for (int e = threadIdx.x; e < cout*cpad; e += 512) {
            int o = e / cpad, c = e - o*cpad;
            int src;
            if (gat[l]) src = (c < 64) ? c + 3 : (c < 67 ? c - 64 : -1);
            else        src = (c < cin) ? c : -1;
            float wf = (src >= 0) ? W[o*cin + src] : 0.0f;
            __half h = __float2half_rn(wf);
            __half lo = __float2half_rn(wf - __half2float(h));
            wth[l*12288 + e] = *reinterpret_cast<uint16_t*>(&h);
            wtl[l*12288 + e] = *reinterpret_cast<uint16_t*>(&lo);
        }
        return;
    }
    int b = blockIdx.x, tid = threadIdx.x;
    const float* px = pc + (size_t)b*3*NN;
    const float* py = px + NN;
    const float* pz = py + NN;
    float x[8], yv[8], z[8], dmin[8];
#pragma unroll
    for (int j = 0; j < 8; j++) {
        int i = tid + j*512;
        x[j] = px[i]; yv[j] = py[i]; z[j] = pz[i]; dmin[j] = 1e10f;
    }
    __shared__ unsigned svu[2][16], siu[2][16];
    int lane = tid & 31, w = tid >> 5, far = 0;
    for (int it = 0; it < MM; it++) {
        int buf = it & 1;
        if (tid == 0) {
            samp[b*MM + it] = far;
            dout[(b*3+0)*MM + it] = px[far];
            dout[(b*3+1)*MM + it] = py[far];
            dout[(b*3+2)*MM + it] = pz[far];
        }
        float cx = px[far], cy = py[far], cz = pz[far];
        float bv = -1.0f; int bi = 0;
#pragma unroll
        for (int j = 0; j < 8; j++) {
            float dx = x[j]-cx, dy = yv[j]-cy, dz = z[j]-cz;
            float d = __fadd_rn(__fadd_rn(__fmul_rn(dx,dx), __fmul_rn(dy,dy)), __fmul_rn(dz,dz));
            float nd = fminf(dmin[j], d);
            dmin[j] = nd;
            if (nd > bv) { bv = nd; bi = tid + j*512; }
        }
        unsigned fb = __float_as_uint(bv);
        unsigned mw = __reduce_max_sync(0xffffffffu, fb);
        unsigned mi = __reduce_min_sync(0xffffffffu, (fb == mw) ? (unsigned)bi : 0xffffffffu);
        if (lane == 0) { svu[buf][w] = mw; siu[buf][w] = mi; }
        __syncthreads();
        unsigned f2 = (lane < 16) ? svu[buf][lane] : 0u;
        unsigned i2 = (lane < 16) ? siu[buf][lane] : 0xffffffffu;
        unsigned m2 = __reduce_max_sync(0xffffffffu, f2);
        far = (int)__reduce_min_sync(0xffffffffu, (f2 == m2) ? i2 : 0xffffffffu);
    }
}

// ---------------- dual-radius ball query ----------------
__global__ __launch_bounds__(256) void ballquery2_kernel(const float* __restrict__ pc,
    const int* __restrict__ samp, int* __restrict__ gidx0, int* __restrict__ gidx1,
    float r2a, float r2b)
{
    extern __shared__ float sh[];
    float* sx = sh; float* sy = sh + NN; float* sz = sh + 2*NN;
    int b = blockIdx.x;
    const float* px = pc + (size_t)b*3*NN;
    for (int i = threadIdx.x; i < NN; i += blockDim.x) {
        sx[i] = px[i]; sy[i] = px[NN+i]; sz[i] = px[2*NN+i];
    }
    __syncthreads();
    int lane = threadIdx.x & 31, wid = threadIdx.x >> 5;
    int mstart = blockIdx.y * 32;
    unsigned lt = (1u << lane) - 1u;
    for (int m = mstart + wid; m < mstart + 32; m += 8) {
        int ci = samp[b*MM + m];
        float cx = sx[ci], cy = sy[ci], cz = sz[ci];
        int cnt0 = 0, cnt1 = 0, f0 = -1, f1 = -1;
        int* out0 = gidx0 + ((size_t)(b*MM + m))*32;
        int* out1 = gidx1 + ((size_t)(b*MM + m))*64;
        for (int base = 0; base < NN && (cnt0 < 32 || cnt1 < 64); base += 32) {
            int i = base + lane;
            float dx = sx[i]-cx, dy = sy[i]-cy, dz = sz[i]-cz;
            float d = __fadd_rn(__fadd_rn(__fmul_rn(dx,dx), __fmul_rn(dy,dy)), __fmul_rn(dz,dz));
            bool ok0 = d < r2a, ok1 = d < r2b;
            unsigned m0 = __ballot_sync(0xffffffffu, ok0);
            unsigned m1 = __ballot_sync(0xffffffffu, ok1);
            if (f0 < 0 && m0) f0 = base + __ffs(m0) - 1;
            if (f1 < 0 && m1) f1 = base + __ffs(m1) - 1;
            int p0 = cnt0 + __popc(m0 & lt);
            int p1 = cnt1 + __popc(m1 & lt);
            if (ok0 && p0 < 32) out0[p0] = i;
            if (ok1 && p1 < 64) out1[p1] = i;
            cnt0 = min(32, cnt0 + __popc(m0));
            cnt1 = min(64, cnt1 + __popc(m1));
        }
        for (int p = cnt0 + lane; p < 32; p += 32) out0[p] = f0;
        for (int p = cnt1 + lane; p < 64; p += 32) out1[p] = f1;
    }
}

// ---------------- tensor-core conv: fp16 activations, half2 BN, W fp16 hi/lo ----------------
template<bool GATHER, bool POOL, int COUTB, int CPAD, int KP>
__global__ __launch_bounds__(256, 2) void conv_mma(
    const __half* __restrict__ xin,
    const uint16_t* __restrict__ Whi, const uint16_t* __restrict__ Wlo,
    const float* __restrict__ bias,
    const float* __restrict__ bns, const float* __restrict__ bnt,
    __half* __restrict__ y, float* __restrict__ ps, float* __restrict__ ps2,
    float* __restrict__ pmax, float* __restrict__ pmin,
    int cstride,
    const float* __restrict__ pc, const __half* __restrict__ fth,
    const float* __restrict__ newpc, const int* __restrict__ gidx,
    int mkshift, int kshift)
{
    constexpr int NK = CPAD/16;
    constexpr int WSTR = CPAD*2 + 16;
    constexpr int XROW = 48, XPLANE = 256*XROW;
    constexpr int WOFF = 2*XPLANE;
    constexpr int MOFF = WOFF + 2*COUTB*WSTR;

    extern __shared__ __align__(16) unsigned char smem[];
    __half2* ss2 = (__half2*)(smem + MOFF);
    __half2* st2 = (__half2*)(smem + MOFF + 512);
    unsigned* sfb = (unsigned*)(smem + MOFF + 1024);
    float* sdx = (float*)(smem + MOFF + 2048);
    float* sdy = (float*)(smem + MOFF + 3072);
    float* sdz = (float*)(smem + MOFF + 4096);
    float* sm1 = (float*)(smem + MOFF + 5120);
    float* sm2 = sm1 + 8*COUTB;
    float* pmx = sm2 + 8*COUTB;
    float* pmn = pmx + 8*COUTB;

    const int tid = threadIdx.x, lane = tid & 31, w = tid >> 5;
    const int pblock = blockIdx.x * 256;
    const int ocbase = blockIdx.y * COUTB;
    const int nblk = gridDim.x;
    const uint16_t* Whi_b = Whi + (size_t)ocbase*CPAD;
    const uint16_t* Wlo_b = Wlo + (size_t)ocbase*CPAD;

    if (GATHER) {
        int p = pblock + tid;
        int bbv = p >> mkshift, mmv = (p >> kshift) & (MM-1);
        int ix = gidx[p];
        sfb[tid] = (unsigned)((bbv*NN + ix) * 64);
        sdx[tid] = pc[(size_t)(bbv*3+0)*NN+ix] - newpc[(size_t)(bbv*3+0)*MM+mmv];
        sdy[tid] = pc[(size_t)(bbv*3+1)*NN+ix] - newpc[(size_t)(bbv*3+1)*MM+mmv];
        sdz[tid] = pc[(size_t)(bbv*3+2)*NN+ix] - newpc[(size_t)(bbv*3+2)*MM+mmv];
    } else {
        if (tid < CPAD/2) {
            ss2[tid] = __floats2half2_rn(bns[2*tid], bns[2*tid+1]);
            st2[tid] = __floats2half2_rn(bnt[2*tid], bnt[2*tid+1]);
        }
    }
    for (int e = tid; e < COUTB*CPAD/2; e += 256) {
        int o = e / (CPAD/2), cp = e - o*(CPAD/2);
        *(uint32_t*)(smem + WOFF + o*WSTR + cp*4) = ((const uint32_t*)Whi_b)[e];
        *(uint32_t*)(smem + WOFF + COUTB*WSTR + o*WSTR + cp*4) = ((const uint32_t*)Wlo_b)[e];
    }
    __syncthreads();

    uint2 hr[4];
    auto stage_load = [&](int kc) {
#pragma unroll
        for (int i = 0; i < 4; i++) {
            int e = tid + i*256, pos = e >> 2, c4 = e & 3;
            if (GATHER) {
                if (kc < 4) hr[i] = *(const uint2*)&fth[sfb[pos] + kc*16 + c4*4];
            } else {
                hr[i] = *(const uint2*)&xin[(size_t)(pblock+pos)*CPAD + kc*16 + c4*4];
            }
        }
    };
    auto stage_conv = [&](int kc, int buf) {
        unsigned char* xh = smem + buf*XPLANE;
#pragma unroll
        for (int i = 0; i < 4; i++) {
            int e = tid + i*256, pos = e >> 2, c4 = e & 3;
            uint2 o2v;
            if (GATHER) {
                if (kc < 4) o2v = hr[i];
                else if (c4 == 0) {
                    __half2 a = __floats2half2_rn(sdx[pos], sdy[pos]);
                    __half2 b = __floats2half2_rn(sdz[pos], 0.f);
                    o2v = make_uint2(*(uint32_t*)&a, *(uint32_t*)&b);
                } else o2v = make_uint2(0u, 0u);
            } else {
                int h0 = (kc*16 + c4*4) >> 1;
                __half2 v0 = *(__half2*)&hr[i].x;
                __half2 v1 = *(__half2*)&hr[i].y;
                v0 = __hfma2_relu(v0, ss2[h0],   st2[h0]);
                v1 = __hfma2_relu(v1, ss2[h0+1], st2[h0+1]);
                o2v = make_uint2(*(uint32_t*)&v0, *(uint32_t*)&v1);
            }
            *(uint2*)(xh + pos*XROW + c4*8) = o2v;
        }
    };

    const uint32_t base = smem_u32(smem);
    const uint32_t aoff = base + (uint32_t)((w*32 + (lane & 15))*XROW + (lane >> 4)*16);
    const uint32_t boff = base + WOFF +
        (uint32_t)((((lane >> 4) & 1)*8 + (lane & 7))*WSTR + ((lane >> 3) & 1)*16);

    float acc[2][COUTB/8][4];
#pragma unroll
    for (int t = 0; t < 2; t++)
#pragma unroll
        for (int n = 0; n < COUTB/8; n++)
#pragma unroll
            for (int c = 0; c < 4; c++) acc[t][n][c] = 0.f;

    stage_load(0); stage_conv(0, 0);
    __syncthreads();

    for (int kc = 0; kc < NK; kc++) {
        int buf = kc & 1;
        if (kc + 1 < NK) stage_load(kc + 1);
        uint32_t ah[2][4], bh[COUTB/16][4], bl[COUTB/16][4];
#pragma unroll
        for (int t = 0; t < 2; t++)
            LDSMX4(ah[t], aoff + t*16*XROW + buf*XPLANE);
#pragma unroll
        for (int j = 0; j < COUTB/16; j++) {
            LDSMX4(bh[j], boff + j*16*WSTR + kc*32);
            LDSMX4(bl[j], boff + COUTB*WSTR + j*16*WSTR + kc*32);
        }
#pragma unroll
        for (int j = 0; j < COUTB/16; j++)
#pragma unroll
            for (int t = 0; t < 2; t++) {
                MMAH(acc[t][2*j],   ah[t], bh[j][0], bh[j][1]);
                MMAH(acc[t][2*j+1], ah[t], bh[j][2], bh[j][3]);
            }
#pragma unroll
        for (int j = 0; j < COUTB/16; j++)
#pragma unroll
            for (int t = 0; t < 2; t++) {
                MMAH(acc[t][2*j],   ah[t], bl[j][0], bl[j][1]);
                MMAH(acc[t][2*j+1], ah[t], bl[j][2], bl[j][3]);
            }
        if (kc + 1 < NK) stage_conv(kc + 1, buf ^ 1);
        __syncthreads();
    }

    const int q = lane >> 2, r2i = (lane & 3)*2;
#pragma unroll
    for (int nt = 0; nt < COUTB/8; nt++) {
        int ocl = nt*8 + r2i;
        int oc  = ocbase + ocl;
        float2 bv = *(const float2*)&bias[oc];
        float s1x = 0.f, s1y = 0.f, s2x = 0.f, s2y = 0.f;
        float mxx = -1e30f, mxy = -1e30f, mnx = 1e30f, mny = 1e30f;
#pragma unroll
        for (int t = 0; t < 2; t++) {
            float2 c01 = make_float2(acc[t][nt][0]+bv.x, acc[t][nt][1]+bv.y);
            float2 c23 = make_float2(acc[t][nt][2]+bv.x, acc[t][nt][3]+bv.y);
            if (!POOL) {
                __half2 h01 = __floats2half2_rn(c01.x, c01.y);
                __half2 h23 = __floats2half2_rn(c23.x, c23.y);
                *(__half2*)&y[(size_t)(pblock + w*32 + t*16 + q)*cstride + oc]     = h01;
                *(__half2*)&y[(size_t)(pblock + w*32 + t*16 + q + 8)*cstride + oc] = h23;
                c01 = __half22float2(h01);   // stats over what next layer sees
                c23 = __half22float2(h23);
            }
            s1x += c01.x + c23.x;  s1y += c01.y + c23.y;
            s2x += c01.x*c01.x + c23.x*c23.x;
            s2y += c01.y*c01.y + c23.y*c23.y;
            mxx = fmaxf(mxx, fmaxf(c01.x, c23.x)); mxy = fmaxf(mxy, fmaxf(c01.y, c23.y));
            mnx = fminf(mnx, fminf(c01.x, c23.x)); mny = fminf(mny, fminf(c01.y, c23.y));
        }
#pragma unroll
        for (int o2 = 4; o2 <= 16; o2 <<= 1) {
            s1x += __shfl_xor_sync(0xffffffffu, s1x, o2);
            s1y += __shfl_xor_sync(0xffffffffu, s1y, o2);
            s2x += __shfl_xor_sync(0xffffffffu, s2x, o2);
            s2y += __shfl_xor_sync(0xffffffffu, s2y, o2);
            if (POOL) {
                mxx = fmaxf(mxx, __shfl_xor_sync(0xffffffffu, mxx, o2));
                mxy = fmaxf(mxy, __shfl_xor_sync(0xffffffffu, mxy, o2));
                mnx = fminf(mnx, __shfl_xor_sync(0xffffffffu, mnx, o2));
                mny = fminf(mny, __shfl_xor_sync(0xffffffffu, mny, o2));
            }
        }
        if (q == 0) {
            sm1[w*COUTB + ocl] = s1x; sm1[w*COUTB + ocl + 1] = s1y;
            sm2[w*COUTB + ocl] = s2x; sm2[w*COUTB + ocl + 1] = s2y;
            if (POOL) {
                if (KP == 32) {
                    size_t g = (size_t)(pblock >> 5) + w;
                    pmax[(size_t)oc*GCOUNT + g] = mxx; pmax[(size_t)(oc+1)*GCOUNT + g] = mxy;
                    pmin[(size_t)oc*GCOUNT + g] = mnx; pmin[(size_t)(oc+1)*GCOUNT + g] = mny;
                } else {
                    pmx[w*COUTB + ocl] = mxx; pmx[w*COUTB + ocl + 1] = mxy;
                    pmn[w*COUTB + ocl] = mnx; pmn[w*COUTB + ocl + 1] = mny;
                }
            }
        }
    }
    __syncthreads();
    for (int e = tid; e < COUTB; e += 256) {
        float a = 0.f, b2 = 0.f;
#pragma unroll
        for (int wi = 0; wi < 8; wi++) { a += sm1[wi*COUTB + e]; b2 += sm2[wi*COUTB + e]; }
        ps [(size_t)(ocbase + e)*nblk + blockIdx.x] = a;
        ps2[(size_t)(ocbase + e)*nblk + blockIdx.x] = b2;
    }
    if (POOL && KP == 64) {
        for (int e = tid; e < COUTB*4; e += 256) {
            int g = e / COUTB, ocl = e - g*COUTB;
            float mx = fmaxf(pmx[(g*2)*COUTB + ocl], pmx[(g*2+1)*COUTB + ocl]);
            float mn = fminf(pmn[(g*2)*COUTB + ocl], pmn[(g*2+1)*COUTB + ocl]);
            size_t gg = (size_t)(pblock >> 6) + g;
            pmax[(size_t)(ocbase + ocl)*GCOUNT + gg] = mx;
            pmin[(size_t)(ocbase + ocl)*GCOUNT + gg] = mn;
        }
    }
}

// ---------------- finalize BN ----------------
__global__ __launch_bounds__(256) void finalize_kernel(const float* __restrict__ ps,
    const float* __restrict__ ps2, int nblk, float invP,
    const float* __restrict__ gamma, const float* __restrict__ beta,
    float* __restrict__ s, float* __restrict__ t)
{
    int c = blockIdx.x;
    float a = 0.f, b = 0.f;
    for (int i = threadIdx.x; i < nblk; i += 256) {
        a += ps [(size_t)c*nblk + i];
        b += ps2[(size_t)c*nblk + i];
    }
#pragma unroll
    for (int off = 16; off > 0; off >>= 1) {
        a += __shfl_down_sync(0xffffffffu, a, off);
        b += __shfl_down_sync(0xffffffffu, b, off);
    }
    __shared__ float sa[8], sb[8];
    int lane = threadIdx.x & 31, w = threadIdx.x >> 5;
    if (lane == 0) { sa[w] = a; sb[w] = b; }
    __syncthreads();
    if (threadIdx.x < 8) {
        a = sa[threadIdx.x]; b = sb[threadIdx.x];
#pragma unroll
        for (int off = 4; off > 0; off >>= 1) {
            a += __shfl_down_sync(0xffu, a, off);
            b += __shfl_down_sync(0xffu, b, off);
        }
        if (threadIdx.x == 0) {
            float mu = a * invP;
            float var = b * invP - mu*mu;
            float sc = gamma[c] / sqrtf(var + 1e-5f);
            s[c] = sc;
            t[c] = beta[c] - mu * sc;
        }
    }
}

// ---------------- pool apply ----------------
__global__ __launch_bounds__(256) void pool_apply_kernel(const float* __restrict__ pmax,
    const float* __restrict__ pmin, const float* __restrict__ s, const float* __restrict__ t,
    float* __restrict__ out, int chbase)
{
    int gid = blockIdx.x*256 + threadIdx.x;
    int oc = gid >> 14, g = gid & 16383;
    float sc = s[oc], tc = t[oc];
    float v = (sc > 0.f) ? pmax[gid] : pmin[gid];
    float r = fmaxf(v*sc + tc, 0.f);
    out[OUT_OFS + ((size_t)((g >> 10)*256 + chbase + oc))*MM + (g & 1023)] = r;
}

// ---------------- host ----------------
extern "C" void kernel_launch(void* const* d_in, const int* in_sizes, int n_in,
                              void* d_out, int out_size)
{
    const float* pc   = (const float*)d_in[0];
    const float* feat = (const float*)d_in[1];
    const float *bp[6], *gp[6], *bep[6];
    WPtrs wargs;
    for (int i = 0; i < 6; i++) {
        wargs.w[i] = (const float*)d_in[2 + 4*i];
        bp[i]  = (const float*)d_in[3 + 4*i];
        gp[i]  = (const float*)d_in[4 + 4*i];
        bep[i] = (const float*)d_in[5 + 4*i];
    }
    float* out = (float*)d_out;

    int *samp, *idx0, *idx1;
    float *sv, *tv, *ps, *ps2, *pmax, *pmin;
    __half *bufA, *bufB, *fth;
    uint16_t *wth, *wtl;
    cudaGetSymbolAddress((void**)&samp, g_samp);
    cudaGetSymbolAddress((void**)&idx0, g_idx0);
    cudaGetSymbolAddress((void**)&idx1, g_idx1);
    cudaGetSymbolAddress((void**)&bufA, g_bufA);
    cudaGetSymbolAddress((void**)&bufB, g_bufB);
    cudaGetSymbolAddress((void**)&fth,  g_fth);
    cudaGetSymbolAddress((void**)&sv,   g_s);
    cudaGetSymbolAddress((void**)&tv,   g_t);
    cudaGetSymbolAddress((void**)&ps,   g_ps);
    cudaGetSymbolAddress((void**)&ps2,  g_ps2);
    cudaGetSymbolAddress((void**)&pmax, g_pmax);
    cudaGetSymbolAddress((void**)&pmin, g_pmin);
    cudaGetSymbolAddress((void**)&wth,  g_wth);
    cudaGetSymbolAddress((void**)&wtl,  g_wtl);

    const int sm_A = 24576 + 2*64*176 + 5120 + 8192;   // gather 64x80 = 60416
    const int sm_B = 24576 + 2*64*144 + 5120 + 8192;   // 64x64        = 56320
    const int sm_D = 24576 + 2*48*144 + 5120 + 6144;   // 48x64        = 49664
    const int sm_E = 24576 + 2*64*208 + 5120 + 8192;   // 64x96 pool   = 64512
    cudaFuncSetAttribute(conv_mma<true,false,64,80,32>,  cudaFuncAttributeMaxDynamicSharedMemorySize, sm_A);
    cudaFuncSetAttribute(conv_mma<false,false,64,64,32>, cudaFuncAttributeMaxDynamicSharedMemorySize, sm_B);
    cudaFuncSetAttribute(conv_mma<false,true,64,64,32>,  cudaFuncAttributeMaxDynamicSharedMemorySize, sm_B);
    cudaFuncSetAttribute(conv_mma<false,false,48,64,32>, cudaFuncAttributeMaxDynamicSharedMemorySize, sm_D);
    cudaFuncSetAttribute(conv_mma<false,true,64,96,64>,  cudaFuncAttributeMaxDynamicSharedMemorySize, sm_E);

    ftr_kernel<<<dim3(128, 2, BB), dim3(32, 8)>>>(feat, fth);
    fps_kernel<<<BB + 6, 512>>>(pc, samp, out, wargs, wth, wtl);
    ballquery2_kernel<<<dim3(BB,32), 256, 3*NN*sizeof(float)>>>(pc, samp, idx0, idx1, 0.01f, 0.04f);

    const int nb0 = P0/256, nb1 = P1/256;

    // branch 1 first (bigger): 67->64->96->128, K=64
    conv_mma<true,false,64,80,32><<<dim3(nb1,1), 256, sm_A>>>(nullptr, wth+3*12288, wtl+3*12288,
        bp[3], nullptr, nullptr, bufA, ps, ps2, nullptr, nullptr, 64, pc, fth, out, idx1, 16, 6);
    finalize_kernel<<<64, 256>>>(ps, ps2, nb1, 1.f/P1, gp[3], bep[3], sv, tv);
    conv_mma<false,false,48,64,32><<<dim3(nb1,2), 256, sm_D>>>(bufA, wth+4*12288, wtl+4*12288,
        bp[4], sv, tv, bufB, ps, ps2, nullptr, nullptr, 96, nullptr, nullptr, nullptr, nullptr, 0, 0);
    finalize_kernel<<<96, 256>>>(ps, ps2, nb1, 1.f/P1, gp[4], bep[4], sv, tv);
    conv_mma<false,true,64,96,64><<<dim3(nb1,2), 256, sm_E>>>(bufB, wth+5*12288, wtl+5*12288,
        bp[5], sv, tv, nullptr, ps, ps2, pmax, pmin, 128, nullptr, nullptr, nullptr, nullptr, 0, 0);
    finalize_kernel<<<128, 256>>>(ps, ps2, nb1, 1.f/P1, gp[5], bep[5], sv, tv);
    pool_apply_kernel<<<(128*GCOUNT)/256, 256>>>(pmax, pmin, sv, tv, out, 128);

    // branch 0: 67->64->64->128, K=32
    conv_mma<true,false,64,80,32><<<dim3(nb0,1), 256, sm_A>>>(nullptr, wth+0*12288, wtl+0*12288,
        bp[0], nullptr, nullptr, bufA, ps, ps2, nullptr, nullptr, 64, pc, fth, out, idx0, 15, 5);
    finalize_kernel<<<64, 256>>>(ps, ps2, nb0, 1.f/P0, gp[0], bep[0], sv, tv);
    conv_mma<false,false,64,64,32><<<dim3(nb0,1), 256, sm_B>>>(bufA, wth+1*12288, wtl+1*12288,
        bp[1], sv, tv, bufB, ps, ps2, nullptr, nullptr, 64, nullptr, nullptr, nullptr, nullptr, 0, 0);
    finalize_kernel<<<64, 256>>>(ps, ps2, nb0, 1.f/P0, gp[1], bep[1], sv, tv);
    conv_mma<false,true,64,64,32><<<dim3(nb0,2), 256, sm_B>>>(bufB, wth+2*12288, wtl+2*12288,
        bp[2], sv, tv, nullptr, ps, ps2, pmax, pmin, 128, nullptr, nullptr, nullptr, nullptr, 0, 0);
    finalize_kernel<<<128, 256>>>(ps, ps2, nb0, 1.f/P0, gp[2], bep[2], sv, tv);
    pool_apply_kernel<<<(128*GCOUNT)/256, 256>>>(pmax, pmin, sv, tv, out, 0);
}